// round 7
// baseline (speedup 1.0000x reference)
#include <cuda_runtime.h>

#define TSEQ 2048
#define BATCH 64
#define HID 256
#define NBLOCKS 128
#define NTHREADS 256
#define MTOT (TSEQ * BATCH)          // 131072 rows

#define OUT_LH 67108864UL            // T*B*2H
#define LHN    65536UL               // 4*B*H

typedef unsigned long long ull;

// ---- scratch (device statics are the sanctioned no-alloc path) ----
__device__ float g_zin[4][(size_t)MTOT * 1024];   // precomputed input projections
__device__ float g_hs0f[(size_t)MTOT * HID];
__device__ float g_hs0b[(size_t)MTOT * HID];
__device__ float g_h[2][2][BATCH * HID];          // [parity][dir][b*H + j]
__device__ unsigned g_flags[2][64];               // per-direction per-block step flags

struct Params {
    const float* __restrict__ x;
    const int*   __restrict__ len;
    const float* __restrict__ w[16];
    float*       __restrict__ out;
};

// ---------------- scan-phase shared memory layout (floats) ----------------
// sW  : [16 rows][268] (halves at +0 / +132)     : 0     .. 4288
// sHb : [64][276] (4-float gap at k=128)         : 4288  .. 21952
// zp  : [2][64][20]                              : 21952 .. 24512
// hb  : [4][65]                                  : 24512 .. 24772
// sB  : [16]                                     : 24772 .. 24788
// sLen: [64] ints                                : 24788 .. 24852
#define SM_HB   4288
#define SM_ZP   21952
#define SM_HBUF 24512
#define SM_B    24772
#define SM_LEN  24788
#define SMEM_FLOATS 24852
#define SMEM_BYTES (SMEM_FLOATS * 4)

__device__ __forceinline__ ull pck(float lo, float hi) {
    ull r;
    asm("mov.b64 %0, {%1, %2};" : "=l"(r) : "f"(lo), "f"(hi));
    return r;
}
__device__ __forceinline__ void unpck(float& lo, float& hi, ull v) {
    asm("mov.b64 {%0, %1}, %2;" : "=f"(lo), "=f"(hi) : "l"(v));
}
__device__ __forceinline__ void fma2(ull& d, ull a, ull b) {
    asm("fma.rn.f32x2 %0, %1, %2, %0;" : "+l"(d) : "l"(a), "l"(b));
}
__device__ __forceinline__ float hsum2(ull v) {
    float lo, hi;
    unpck(lo, hi, v);
    return lo + hi;
}

__device__ __forceinline__ float sigf(float x) {
    return __fdividef(1.f, 1.f + __expf(-x));
}

// flag barrier: every block release-stores its own flag, threads 0..63 acquire-poll all
__device__ __forceinline__ void fbar(unsigned* flags, int own, unsigned ts) {
    __syncthreads();
    if (threadIdx.x == 0)
        asm volatile("st.release.gpu.global.u32 [%0], %1;" :: "l"(flags + own), "r"(ts) : "memory");
    if (threadIdx.x < 64) {
        unsigned v;
        do {
            asm volatile("ld.acquire.gpu.global.u32 %0, [%1];"
                         : "=r"(v) : "l"(flags + threadIdx.x) : "memory");
        } while (v < ts);
    }
    __syncthreads();
}

__global__ void noop_kernel() {}

// =======================================================================
// Bulk GEMM: C[M=131072,1024] = A[M,256] @ W[1024, ldw(first 256 cols)]^T
// tile 128x128, 256 threads, 8x8 per thread via fma.rn.f32x2
// =======================================================================
__global__ void __launch_bounds__(256, 2)
gemm_k256(const float* __restrict__ A, const float* __restrict__ W, int ldw,
          float* __restrict__ C)
{
    __shared__ float sA[2][16][132];
    __shared__ float sB[2][16][132];
    const int tid = threadIdx.x;
    const int m0 = blockIdx.y << 7;
    const int n0 = blockIdx.x << 7;
    const int tx = tid & 15, ty = tid >> 4;
    const int lr = tid >> 2;               // 0..63
    const int lk = (tid & 3) << 2;         // 0,4,8,12

    const float* Ap0 = A + (size_t)(m0 + lr) * 256 + lk;
    const float* Ap1 = Ap0 + (size_t)64 * 256;
    const float* Wp0 = W + (size_t)(n0 + lr) * ldw + lk;
    const float* Wp1 = Wp0 + (size_t)64 * ldw;

    ull acc2[8][4];
#pragma unroll
    for (int i = 0; i < 8; ++i)
#pragma unroll
        for (int j = 0; j < 4; ++j) acc2[i][j] = 0ull;

    float4 ra0, ra1, rb0, rb1;

#define GLOAD(kb) do { int k0_ = (kb) << 4;                         \
        ra0 = __ldg((const float4*)(Ap0 + k0_));                    \
        ra1 = __ldg((const float4*)(Ap1 + k0_));                    \
        rb0 = __ldg((const float4*)(Wp0 + k0_));                    \
        rb1 = __ldg((const float4*)(Wp1 + k0_)); } while (0)

#define SSTORE(buf) do {                                            \
        float* a_ = &sA[buf][lk][lr];                               \
        a_[0] = ra0.x; a_[132] = ra0.y; a_[264] = ra0.z; a_[396] = ra0.w; \
        a_[64] = ra1.x; a_[196] = ra1.y; a_[328] = ra1.z; a_[460] = ra1.w; \
        float* b_ = &sB[buf][lk][lr];                               \
        b_[0] = rb0.x; b_[132] = rb0.y; b_[264] = rb0.z; b_[396] = rb0.w; \
        b_[64] = rb1.x; b_[196] = rb1.y; b_[328] = rb1.z; b_[460] = rb1.w; } while (0)

    GLOAD(0); SSTORE(0); __syncthreads();

    for (int kb = 0; kb < 16; ++kb) {
        const int cur = kb & 1;
        if (kb < 15) GLOAD(kb + 1);
#pragma unroll
        for (int k = 0; k < 16; ++k) {
            float4 a0 = *(const float4*)&sA[cur][k][ty * 8];
            float4 a1 = *(const float4*)&sA[cur][k][ty * 8 + 4];
            ulonglong2 bq0 = *(const ulonglong2*)&sB[cur][k][tx * 8];
            ulonglong2 bq1 = *(const ulonglong2*)&sB[cur][k][tx * 8 + 4];
            float am[8] = {a0.x, a0.y, a0.z, a0.w, a1.x, a1.y, a1.z, a1.w};
#pragma unroll
            for (int i = 0; i < 8; ++i) {
                ull ap = pck(am[i], am[i]);
                fma2(acc2[i][0], ap, bq0.x);
                fma2(acc2[i][1], ap, bq0.y);
                fma2(acc2[i][2], ap, bq1.x);
                fma2(acc2[i][3], ap, bq1.y);
            }
        }
        if (kb < 15) { SSTORE(cur ^ 1); __syncthreads(); }
    }

#pragma unroll
    for (int i = 0; i < 8; ++i) {
        size_t row = (size_t)(m0 + ty * 8 + i);
        ulonglong2 o0; o0.x = acc2[i][0]; o0.y = acc2[i][1];
        ulonglong2 o1; o1.x = acc2[i][2]; o1.y = acc2[i][3];
        *(ulonglong2*)(C + row * 1024 + n0 + tx * 8)     = o0;
        *(ulonglong2*)(C + row * 1024 + n0 + tx * 8 + 4) = o1;
    }
}

// =======================================================================
// Persistent recurrent scan (one launch per layer, K=256)
// k-pair fma.rn.f32x2: acc lanes carry even/odd-k partial sums, no packs.
// 128 blocks: 64 per direction, each owns 4 hidden units (16 gate rows)
// thread tile: 4 gate-rows x 2 batches x K-half(128)
// =======================================================================
__global__ void __launch_bounds__(NTHREADS, 1)
scan_kernel(Params p, int layer, unsigned tsbase)
{
    extern __shared__ float sm[];
    float* sW  = sm;                    // [16 rows][268], halves at +0/+132
    float* sHb = sm + SM_HB;            // [b][276] with 4-float gap at k=128
    float* zp  = sm + SM_ZP;            // [half][b][20]
    float* hb  = sm + SM_HBUF;          // [4][65]
    float* sB  = sm + SM_B;             // [16]
    int*   sLen= (int*)(sm + SM_LEN);   // [64]

    const int tid  = threadIdx.x;
    const int dir  = blockIdx.x >> 6;
    const int own  = blockIdx.x & 63;
    const int j0   = own << 2;
    const int rq   = tid & 3;           // gate
    const int half = (tid >> 2) & 1;    // K-half
    const int bp   = tid >> 3;          // batch pair 0..31
    const int b0   = bp << 1, b1 = b0 + 1;
    const int uj   = tid >> 6, ub = tid & 63;
    unsigned* flags = g_flags[dir];

    if (tid < BATCH) sLen[tid] = p.len[tid];

    const float* whh = p.w[layer * 8 + dir * 4 + 1];
    const float* bih = p.w[layer * 8 + dir * 4 + 2];
    const float* bhh = p.w[layer * 8 + dir * 4 + 3];

    // weights transposed: sW[r][k-pos], k-pos = k<128 ? k : 132+(k-128)
    for (int r = 0; r < 16; ++r) {
        int grow = ((r >> 2) << 8) + j0 + (r & 3);
        const float* wsrc = whh + (size_t)grow * HID;
        int k = tid;   // NTHREADS == HID
        sW[r * 268 + (k >= 128 ? k + 4 : k)] = wsrc[k];
    }
    if (tid < 16) {
        int grow = ((tid >> 2) << 8) + j0 + (tid & 3);
        sB[tid] = bih[grow] + bhh[grow];
    }
    g_h[0][dir][(tid & 63) * HID + j0 + (tid >> 6)] = 0.f;
    float creg = 0.f;
    __syncthreads();

    // per-thread bias (added once, on half 0 only)
    float bi0 = half ? 0.f : sB[rq * 4 + 0];
    float bi1 = half ? 0.f : sB[rq * 4 + 1];
    float bi2 = half ? 0.f : sB[rq * 4 + 2];
    float bi3 = half ? 0.f : sB[rq * 4 + 3];

    // zin sources + per-example time modes (0: t, 1: (t+len)%T, 2: (t+T-len)%T)
    const float *srcA, *srcB = nullptr;
    int modeA, modeB = 0;
    if (layer == 0)      { srcA = g_zin[dir]; modeA = dir ? 1 : 0; }
    else if (dir == 0)   { srcA = g_zin[0]; modeA = 0; srcB = g_zin[1]; modeB = 2; }
    else                 { srcA = g_zin[2]; modeA = 1; srcB = g_zin[3]; modeB = 0; }
    const float* zsrc = half ? srcB : srcA;
    const int    zmode = half ? modeB : modeA;
    const int    zcol  = (rq << 8) + j0;

    auto zgather = [&](int s, float4& zA, float4& zB) {
        if (!zsrc) { zA = make_float4(0,0,0,0); zB = zA; return; }
        int t = dir ? (TSEQ - 1 - s) : s;
        int tA = t, tB = t;
        int lb0 = sLen[b0], lb1 = sLen[b1];
        if (zmode == 1)      { tA = t + lb0;        tB = t + lb1; }
        else if (zmode == 2) { tA = t + TSEQ - lb0; tB = t + TSEQ - lb1; }
        if (tA >= TSEQ) tA -= TSEQ;
        if (tB >= TSEQ) tB -= TSEQ;
        zA = __ldg((const float4*)(zsrc + ((size_t)tA * BATCH + b0) * 1024 + zcol));
        zB = __ldg((const float4*)(zsrc + ((size_t)tB * BATCH + b1) * 1024 + zcol));
    };

    unsigned ts = tsbase;
    fbar(flags, own, ++ts);   // h zeros visible across the direction

    float4 znA, znB;
    zgather(0, znA, znB);     // prime the z pipeline

    const float* wbase = sW + (rq * 4) * 268 + half * 132;
    const float* hB0   = sHb + b0 * 276 + half * 132;
    const float* hB1   = hB0 + 276;

    for (int s = 0; s < TSEQ; ++s) {
        const int par = s & 1;
        const int t = dir ? (TSEQ - 1 - s) : s;
        const float* hsrc = &g_h[par][dir][0];

        float4 zA = znA, zB = znB;
        if (s + 1 < TSEQ) zgather(s + 1, znA, znB);

        // ---- stage h into smem (gap layout: quad b*69 + kq + (kq>>5)) ----
#pragma unroll
        for (int i = 0; i < 16; ++i) {
            int f = (i << 8) + tid;
            int b = f >> 6, kq = f & 63;
            float4 v = __ldcg((const float4*)(hsrc + b * HID) + kq);
            ((float4*)sHb)[b * 69 + kq + (kq >> 5)] = v;
        }
        __syncthreads();

        // ---- recurrent GEMM: k-pair f32x2, 4 rows x 2 batches, K-half ----
        // acc lanes = (even-k partial, odd-k partial); init lo lane with z+bias
        ull a00 = pck(zA.x + bi0, 0.f), a10 = pck(zA.y + bi1, 0.f);
        ull a20 = pck(zA.z + bi2, 0.f), a30 = pck(zA.w + bi3, 0.f);
        ull a01 = pck(zB.x + bi0, 0.f), a11 = pck(zB.y + bi1, 0.f);
        ull a21 = pck(zB.z + bi2, 0.f), a31 = pck(zB.w + bi3, 0.f);
#pragma unroll 8
        for (int g = 0; g < 32; ++g) {
            ulonglong2 w0 = *(const ulonglong2*)(wbase + 0 * 268 + g * 4);
            ulonglong2 w1 = *(const ulonglong2*)(wbase + 1 * 268 + g * 4);
            ulonglong2 w2 = *(const ulonglong2*)(wbase + 2 * 268 + g * 4);
            ulonglong2 w3 = *(const ulonglong2*)(wbase + 3 * 268 + g * 4);
            ulonglong2 h0 = *(const ulonglong2*)(hB0 + g * 4);
            ulonglong2 h1 = *(const ulonglong2*)(hB1 + g * 4);
            fma2(a00, w0.x, h0.x); fma2(a00, w0.y, h0.y);
            fma2(a10, w1.x, h0.x); fma2(a10, w1.y, h0.y);
            fma2(a20, w2.x, h0.x); fma2(a20, w2.y, h0.y);
            fma2(a30, w3.x, h0.x); fma2(a30, w3.y, h0.y);
            fma2(a01, w0.x, h1.x); fma2(a01, w0.y, h1.y);
            fma2(a11, w1.x, h1.x); fma2(a11, w1.y, h1.y);
            fma2(a21, w2.x, h1.x); fma2(a21, w2.y, h1.y);
            fma2(a31, w3.x, h1.x); fma2(a31, w3.y, h1.y);
        }
        {
            float* zr0 = zp + (half * 64 + b0) * 20 + rq * 4;
            float* zr1 = zp + (half * 64 + b1) * 20 + rq * 4;
            *(ull*)(zr0)     = pck(hsum2(a00), hsum2(a10));
            *(ull*)(zr0 + 2) = pck(hsum2(a20), hsum2(a30));
            *(ull*)(zr1)     = pck(hsum2(a01), hsum2(a11));
            *(ull*)(zr1 + 2) = pck(hsum2(a21), hsum2(a31));
        }
        __syncthreads();

        // ---- cell update: thread owns (uj, ub); c stays in register ----
        {
            const float* z0 = zp + ub * 20;            // half 0
            const float* z1 = zp + (64 + ub) * 20;     // half 1
            float zi = z0[0  + uj] + z1[0  + uj];
            float zf = z0[4  + uj] + z1[4  + uj];
            float zg = z0[8  + uj] + z1[8  + uj];
            float zo = z0[12 + uj] + z1[12 + uj];
            float ig = sigf(zi), fg = sigf(zf), gg = tanhf(zg), og = sigf(zo);
            creg = fg * creg + ig * gg;
            float h = og * tanhf(creg);
            hb[uj * 65 + ub] = h;
            int lb = sLen[ub];
            bool trig = dir ? (t == TSEQ - lb) : (t == lb - 1);
            if (trig) {
                size_t o = OUT_LH + ((size_t)(layer * 2 + dir) * BATCH + ub) * HID + j0 + uj;
                p.out[o] = h;
                p.out[o + LHN] = creg;
            }
        }
        __syncthreads();

        // ---- write h for next step (+ history / output) ----
        {
            int j = tid & 3, b = tid >> 2;
            float hv = hb[j * 65 + b];
            g_h[par ^ 1][dir][b * HID + j0 + j] = hv;
            if (layer == 0) {
                float* hs = dir ? g_hs0b : g_hs0f;
                hs[((size_t)t * BATCH + b) * HID + j0 + j] = hv;
            } else {
                int lb = sLen[b];
                int tm = t, col = j0 + j;
                if (dir) { tm = t + lb; if (tm >= TSEQ) tm -= TSEQ; col += HID; }
                p.out[((size_t)tm * BATCH + b) * (2 * HID) + col] = (tm < lb) ? hv : 0.f;
            }
        }

        fbar(flags, own, ++ts);
    }
}

extern "C" void kernel_launch(void* const* d_in, const int* in_sizes, int n_in,
                              void* d_out, int out_size) {
    Params P;
    P.x   = (const float*)d_in[0];
    P.len = (const int*)d_in[1];
    for (int i = 0; i < 16; ++i) P.w[i] = (const float*)d_in[2 + i];
    P.out = (float*)d_out;

    void *zp_, *hsf_, *hsb_, *fl_;
    cudaGetSymbolAddress(&zp_,  g_zin);
    cudaGetSymbolAddress(&hsf_, g_hs0f);
    cudaGetSymbolAddress(&hsb_, g_hs0b);
    cudaGetSymbolAddress(&fl_,  g_flags);
    float* z = (float*)zp_;
    const float* hsf = (const float*)hsf_;
    const float* hsb = (const float*)hsb_;
    const size_t ZN = (size_t)MTOT * 1024;

    cudaFuncSetAttribute(scan_kernel, cudaFuncAttributeMaxDynamicSharedMemorySize, SMEM_BYTES);

    dim3 gg(8, 1024);   // N-tiles x M-tiles

    cudaMemsetAsync(fl_, 0, sizeof(g_flags));                 // launch 1 (1-based ncu count)

    // layer-0 input projections (K=256)
    gemm_k256<<<gg, 256>>>(P.x, P.w[0], 256, z);              // launch 2 (fwd)
    gemm_k256<<<gg, 256>>>(P.x, P.w[4], 256, z + ZN);         // launch 3 (bwd)

    noop_kernel<<<1, 32>>>();                                 // launch 4 (ncu alignment)

    scan_kernel<<<NBLOCKS, NTHREADS, SMEM_BYTES>>>(P, 0, 0u); // launch 5 <- ncu -s 5 target

    // layer-1 input projections: K=512 split into two K=256 halves
    gemm_k256<<<gg, 256>>>(hsf, P.w[8],        512, z);            // fwd, hsf-half
    gemm_k256<<<gg, 256>>>(hsb, P.w[8]  + 256, 512, z + ZN);       // fwd, hsb-half
    gemm_k256<<<gg, 256>>>(hsf, P.w[12],       512, z + 2 * ZN);   // bwd, hsf-half
    gemm_k256<<<gg, 256>>>(hsb, P.w[12] + 256, 512, z + 3 * ZN);   // bwd, hsb-half

    scan_kernel<<<NBLOCKS, NTHREADS, SMEM_BYTES>>>(P, 1, 8192u);
}

// round 8
// speedup vs baseline: 1.0561x; 1.0561x over previous
#include <cuda_runtime.h>

#define TSEQ 2048
#define BATCH 64
#define HID 256
#define NBLOCKS 128
#define NTHREADS 256
#define MTOT (TSEQ * BATCH)          // 131072 rows

#define OUT_LH 67108864UL            // T*B*2H
#define LHN    65536UL               // 4*B*H

typedef unsigned long long ull;

// ---- scratch (device statics are the sanctioned no-alloc path) ----
__device__ float g_zin[4][(size_t)MTOT * 1024];   // precomputed input projections
__device__ float g_hs0f[(size_t)MTOT * HID];
__device__ float g_hs0b[(size_t)MTOT * HID];
__device__ float g_h[2][2][BATCH * HID];          // [parity][dir][b*H + j]

struct Sync {
    unsigned flags[2][64];   // per-direction per-block arrival generation
    unsigned gen[2][32];     // broadcast word per direction (padded line)
};
__device__ Sync g_sync;

struct Params {
    const float* __restrict__ x;
    const int*   __restrict__ len;
    const float* __restrict__ w[16];
    float*       __restrict__ out;
};

// ---------------- scan-phase shared memory layout (floats) ----------------
// sWt : [half][128][16] + 16-float inter-half gap  : 0     .. 4112
// sHb : [64][276] (4-float gap at k=128)           : 4112  .. 21776
// zp  : [2][64][20]                                : 21776 .. 24336
// hb  : [4][65]                                    : 24336 .. 24596
// sB  : [16]                                       : 24596 .. 24612
// sLen: [64] ints                                  : 24612 .. 24676
#define SM_HB   4112
#define SM_ZP   21776
#define SM_HBUF 24336
#define SM_B    24596
#define SM_LEN  24612
#define SMEM_FLOATS 24676
#define SMEM_BYTES (SMEM_FLOATS * 4)

__device__ __forceinline__ ull pck(float lo, float hi) {
    ull r;
    asm("mov.b64 %0, {%1, %2};" : "=l"(r) : "f"(lo), "f"(hi));
    return r;
}
__device__ __forceinline__ void fma2(ull& d, ull a, ull b) {
    asm("fma.rn.f32x2 %0, %1, %2, %0;" : "+l"(d) : "l"(a), "l"(b));
}
__device__ __forceinline__ ull add2(ull a, ull b) {
    ull r;
    asm("add.rn.f32x2 %0, %1, %2;" : "=l"(r) : "l"(a), "l"(b));
    return r;
}

__device__ __forceinline__ float sigf(float x) {
    return __fdividef(1.f, 1.f + __expf(-x));
}

// ---- hierarchical barrier ----
// All blocks release-store a private flag. The direction's root block (own==0)
// polls the 64 distinct flags (64 threads), then release-stores ONE generation
// word; non-root blocks poll that single word with a single thread (L2
// broadcast-friendly). Release/acquire chain is transitive, so every block's
// pre-barrier stores are visible after the gen acquire.
__device__ __forceinline__ void fbar(unsigned* flags, unsigned* gen, int own, unsigned ts) {
    __syncthreads();
    if (threadIdx.x == 0)
        asm volatile("st.release.gpu.global.u32 [%0], %1;" :: "l"(flags + own), "r"(ts) : "memory");
    if (own == 0) {
        if (threadIdx.x < 64) {
            unsigned v;
            do {
                asm volatile("ld.acquire.gpu.global.u32 %0, [%1];"
                             : "=r"(v) : "l"(flags + threadIdx.x) : "memory");
            } while (v < ts);
        }
        __syncthreads();
        if (threadIdx.x == 0)
            asm volatile("st.release.gpu.global.u32 [%0], %1;" :: "l"(gen), "r"(ts) : "memory");
    } else {
        if (threadIdx.x == 0) {
            unsigned v;
            do {
                asm volatile("ld.acquire.gpu.global.u32 %0, [%1];"
                             : "=r"(v) : "l"(gen) : "memory");
            } while (v < ts);
        }
    }
    __syncthreads();
}

__global__ void noop_kernel() {}

// =======================================================================
// Bulk GEMM: C[M=131072,1024] = A[M,256] @ W[1024, ldw(first 256 cols)]^T
// tile 128x128, 256 threads, 8x8 per thread via fma.rn.f32x2
// =======================================================================
__global__ void __launch_bounds__(256, 2)
gemm_k256(const float* __restrict__ A, const float* __restrict__ W, int ldw,
          float* __restrict__ C)
{
    __shared__ float sA[2][16][132];
    __shared__ float sB[2][16][132];
    const int tid = threadIdx.x;
    const int m0 = blockIdx.y << 7;
    const int n0 = blockIdx.x << 7;
    const int tx = tid & 15, ty = tid >> 4;
    const int lr = tid >> 2;               // 0..63
    const int lk = (tid & 3) << 2;         // 0,4,8,12

    const float* Ap0 = A + (size_t)(m0 + lr) * 256 + lk;
    const float* Ap1 = Ap0 + (size_t)64 * 256;
    const float* Wp0 = W + (size_t)(n0 + lr) * ldw + lk;
    const float* Wp1 = Wp0 + (size_t)64 * ldw;

    ull acc2[8][4];
#pragma unroll
    for (int i = 0; i < 8; ++i)
#pragma unroll
        for (int j = 0; j < 4; ++j) acc2[i][j] = 0ull;

    float4 ra0, ra1, rb0, rb1;

#define GLOAD(kb) do { int k0_ = (kb) << 4;                         \
        ra0 = __ldg((const float4*)(Ap0 + k0_));                    \
        ra1 = __ldg((const float4*)(Ap1 + k0_));                    \
        rb0 = __ldg((const float4*)(Wp0 + k0_));                    \
        rb1 = __ldg((const float4*)(Wp1 + k0_)); } while (0)

#define SSTORE(buf) do {                                            \
        float* a_ = &sA[buf][lk][lr];                               \
        a_[0] = ra0.x; a_[132] = ra0.y; a_[264] = ra0.z; a_[396] = ra0.w; \
        a_[64] = ra1.x; a_[196] = ra1.y; a_[328] = ra1.z; a_[460] = ra1.w; \
        float* b_ = &sB[buf][lk][lr];                               \
        b_[0] = rb0.x; b_[132] = rb0.y; b_[264] = rb0.z; b_[396] = rb0.w; \
        b_[64] = rb1.x; b_[196] = rb1.y; b_[328] = rb1.z; b_[460] = rb1.w; } while (0)

    GLOAD(0); SSTORE(0); __syncthreads();

    for (int kb = 0; kb < 16; ++kb) {
        const int cur = kb & 1;
        if (kb < 15) GLOAD(kb + 1);
#pragma unroll
        for (int k = 0; k < 16; ++k) {
            float4 a0 = *(const float4*)&sA[cur][k][ty * 8];
            float4 a1 = *(const float4*)&sA[cur][k][ty * 8 + 4];
            ulonglong2 bq0 = *(const ulonglong2*)&sB[cur][k][tx * 8];
            ulonglong2 bq1 = *(const ulonglong2*)&sB[cur][k][tx * 8 + 4];
            float am[8] = {a0.x, a0.y, a0.z, a0.w, a1.x, a1.y, a1.z, a1.w};
#pragma unroll
            for (int i = 0; i < 8; ++i) {
                ull ap = pck(am[i], am[i]);
                fma2(acc2[i][0], ap, bq0.x);
                fma2(acc2[i][1], ap, bq0.y);
                fma2(acc2[i][2], ap, bq1.x);
                fma2(acc2[i][3], ap, bq1.y);
            }
        }
        if (kb < 15) { SSTORE(cur ^ 1); __syncthreads(); }
    }

#pragma unroll
    for (int i = 0; i < 8; ++i) {
        size_t row = (size_t)(m0 + ty * 8 + i);
        ulonglong2 o0; o0.x = acc2[i][0]; o0.y = acc2[i][1];
        ulonglong2 o1; o1.x = acc2[i][2]; o1.y = acc2[i][3];
        *(ulonglong2*)(C + row * 1024 + n0 + tx * 8)     = o0;
        *(ulonglong2*)(C + row * 1024 + n0 + tx * 8 + 4) = o1;
    }
}

// =======================================================================
// Persistent recurrent scan (one launch per layer, K=256, fma.rn.f32x2)
// 128 blocks: 64 per direction, each owns 4 hidden units (16 gate rows)
// thread tile: 4 gate-rows (2 row-pairs) x 2 batches x K-half(128)
// =======================================================================
__global__ void __launch_bounds__(NTHREADS, 1)
scan_kernel(Params p, int layer, unsigned tsbase)
{
    extern __shared__ float sm[];
    float* sWt = sm;                    // [half][k][16] + 16 gap
    float* sHb = sm + SM_HB;            // [b][276] with 4-float gap at k=128
    float* zp  = sm + SM_ZP;            // [half][b][20]
    float* hb  = sm + SM_HBUF;          // [4][65]
    float* sB  = sm + SM_B;             // [16]
    int*   sLen= (int*)(sm + SM_LEN);   // [64]

    const int tid  = threadIdx.x;
    const int dir  = blockIdx.x >> 6;
    const int own  = blockIdx.x & 63;
    const int j0   = own << 2;
    const int rq   = tid & 3;           // gate
    const int half = (tid >> 2) & 1;    // K-half
    const int bp   = tid >> 3;          // batch pair 0..31
    const int b0   = bp << 1, b1 = b0 + 1;
    const int uj   = tid >> 6, ub = tid & 63;
    unsigned* flags = g_sync.flags[dir];
    unsigned* gen   = g_sync.gen[dir];

    if (tid < BATCH) sLen[tid] = p.len[tid];

    const float* whh = p.w[layer * 8 + dir * 4 + 1];
    const float* bih = p.w[layer * 8 + dir * 4 + 2];
    const float* bhh = p.w[layer * 8 + dir * 4 + 3];

    // weights: sWt[half][k][16] with 16-float gap between halves (bank decouple)
    for (int r = 0; r < 16; ++r) {
        int grow = ((r >> 2) << 8) + j0 + (r & 3);
        const float* wsrc = whh + (size_t)grow * HID;
        for (int k = tid; k < HID; k += NTHREADS)
            sWt[k * 16 + (k >= 128 ? 16 : 0) + r] = wsrc[k];
    }
    if (tid < 16) {
        int grow = ((tid >> 2) << 8) + j0 + (tid & 3);
        sB[tid] = bih[grow] + bhh[grow];
    }
    g_h[0][dir][(tid & 63) * HID + j0 + (tid >> 6)] = 0.f;
    float creg = 0.f;
    __syncthreads();

    // packed bias pairs (added once per step, half 0 only)
    const ull bPlo = half ? 0ull : pck(sB[rq * 4 + 0], sB[rq * 4 + 1]);
    const ull bPhi = half ? 0ull : pck(sB[rq * 4 + 2], sB[rq * 4 + 3]);

    // zin sources + per-example time modes (0: t, 1: (t+len)%T, 2: (t+T-len)%T)
    const float *srcA, *srcB = nullptr;
    int modeA, modeB = 0;
    if (layer == 0)      { srcA = g_zin[dir]; modeA = dir ? 1 : 0; }
    else if (dir == 0)   { srcA = g_zin[0]; modeA = 0; srcB = g_zin[1]; modeB = 2; }
    else                 { srcA = g_zin[2]; modeA = 1; srcB = g_zin[3]; modeB = 0; }
    const float* zsrc = half ? srcB : srcA;
    const int    zmode = half ? modeB : modeA;
    const int    zcol  = (rq << 8) + j0;

    auto zgather = [&](int s, float4& zA, float4& zB) {
        if (!zsrc) { zA = make_float4(0,0,0,0); zB = zA; return; }
        int t = dir ? (TSEQ - 1 - s) : s;
        int tA = t, tB = t;
        int lb0 = sLen[b0], lb1 = sLen[b1];
        if (zmode == 1)      { tA = t + lb0;        tB = t + lb1; }
        else if (zmode == 2) { tA = t + TSEQ - lb0; tB = t + TSEQ - lb1; }
        if (tA >= TSEQ) tA -= TSEQ;
        if (tB >= TSEQ) tB -= TSEQ;
        zA = __ldg((const float4*)(zsrc + ((size_t)tA * BATCH + b0) * 1024 + zcol));
        zB = __ldg((const float4*)(zsrc + ((size_t)tB * BATCH + b1) * 1024 + zcol));
    };

    unsigned ts = tsbase;
    fbar(flags, gen, own, ++ts);   // h zeros visible across the direction

    float4 znA, znB;
    zgather(0, znA, znB);     // prime the z pipeline

    for (int s = 0; s < TSEQ; ++s) {
        const int par = s & 1;
        const int t = dir ? (TSEQ - 1 - s) : s;
        const float* hsrc = &g_h[par][dir][0];

        // current-step z from prefetch; immediately issue next step's gather
        float4 zA = znA, zB = znB;
        if (s + 1 < TSEQ) zgather(s + 1, znA, znB);

        // ---- stage h into smem (gap layout: quad b*69 + kq + (kq>>5)) ----
#pragma unroll
        for (int i = 0; i < 16; ++i) {
            int f = (i << 8) + tid;
            int b = f >> 6, kq = f & 63;
            float4 v = __ldcg((const float4*)(hsrc + b * HID) + kq);
            ((float4*)sHb)[b * 69 + kq + (kq >> 5)] = v;
        }
        __syncthreads();

        // ---- recurrent GEMM: packed row-pairs x 2 batches over K-half ----
        ull c00 = pck(zA.x, zA.y), c01 = pck(zA.z, zA.w);
        ull c10 = pck(zB.x, zB.y), c11 = pck(zB.z, zB.w);
        {
            const float* wbase = sWt + half * 2064 + rq * 4;   // 2064 = 128*16 + 16
            const float* h0 = sHb + b0 * 276 + half * 132;
            const float* h1 = h0 + 276;
#pragma unroll 16
            for (int kk = 0; kk < 128; ++kk) {
                ulonglong2 w = *(const ulonglong2*)(wbase + kk * 16);
                float hv0 = h0[kk], hv1 = h1[kk];
                ull h0p = pck(hv0, hv0);
                ull h1p = pck(hv1, hv1);
                fma2(c00, w.x, h0p); fma2(c01, w.y, h0p);
                fma2(c10, w.x, h1p); fma2(c11, w.y, h1p);
            }
        }
        c00 = add2(c00, bPlo); c01 = add2(c01, bPhi);
        c10 = add2(c10, bPlo); c11 = add2(c11, bPhi);
        {
            float* zr0 = zp + (half * 64 + b0) * 20 + rq * 4;
            float* zr1 = zp + (half * 64 + b1) * 20 + rq * 4;
            *(ull*)(zr0)     = c00;  *(ull*)(zr0 + 2) = c01;
            *(ull*)(zr1)     = c10;  *(ull*)(zr1 + 2) = c11;
        }
        __syncthreads();

        // ---- cell update: thread owns (uj, ub); c stays in register ----
        {
            const float* z0 = zp + ub * 20;            // half 0
            const float* z1 = zp + (64 + ub) * 20;     // half 1
            float zi = z0[0  + uj] + z1[0  + uj];
            float zf = z0[4  + uj] + z1[4  + uj];
            float zg = z0[8  + uj] + z1[8  + uj];
            float zo = z0[12 + uj] + z1[12 + uj];
            float ig = sigf(zi), fg = sigf(zf), gg = tanhf(zg), og = sigf(zo);
            creg = fg * creg + ig * gg;
            float h = og * tanhf(creg);
            hb[uj * 65 + ub] = h;
            int lb = sLen[ub];
            bool trig = dir ? (t == TSEQ - lb) : (t == lb - 1);
            if (trig) {
                size_t o = OUT_LH + ((size_t)(layer * 2 + dir) * BATCH + ub) * HID + j0 + uj;
                p.out[o] = h;
                p.out[o + LHN] = creg;
            }
        }
        __syncthreads();

        // ---- write h for next step (+ history / output) ----
        {
            int j = tid & 3, b = tid >> 2;
            float hv = hb[j * 65 + b];
            g_h[par ^ 1][dir][b * HID + j0 + j] = hv;
            if (layer == 0) {
                float* hs = dir ? g_hs0b : g_hs0f;
                hs[((size_t)t * BATCH + b) * HID + j0 + j] = hv;
            } else {
                int lb = sLen[b];
                int tm = t, col = j0 + j;
                if (dir) { tm = t + lb; if (tm >= TSEQ) tm -= TSEQ; col += HID; }
                p.out[((size_t)tm * BATCH + b) * (2 * HID) + col] = (tm < lb) ? hv : 0.f;
            }
        }

        fbar(flags, gen, own, ++ts);
    }
}

extern "C" void kernel_launch(void* const* d_in, const int* in_sizes, int n_in,
                              void* d_out, int out_size) {
    Params P;
    P.x   = (const float*)d_in[0];
    P.len = (const int*)d_in[1];
    for (int i = 0; i < 16; ++i) P.w[i] = (const float*)d_in[2 + i];
    P.out = (float*)d_out;

    void *zp_, *hsf_, *hsb_, *sy_;
    cudaGetSymbolAddress(&zp_,  g_zin);
    cudaGetSymbolAddress(&hsf_, g_hs0f);
    cudaGetSymbolAddress(&hsb_, g_hs0b);
    cudaGetSymbolAddress(&sy_,  g_sync);
    float* z = (float*)zp_;
    const float* hsf = (const float*)hsf_;
    const float* hsb = (const float*)hsb_;
    const size_t ZN = (size_t)MTOT * 1024;

    cudaFuncSetAttribute(scan_kernel, cudaFuncAttributeMaxDynamicSharedMemorySize, SMEM_BYTES);

    dim3 gg(8, 1024);   // N-tiles x M-tiles

    cudaMemsetAsync(sy_, 0, sizeof(Sync));                    // launch 1 (ncu counts it)

    // layer-0 input projections (K=256)
    gemm_k256<<<gg, 256>>>(P.x, P.w[0], 256, z);              // launch 2 (fwd)
    gemm_k256<<<gg, 256>>>(P.x, P.w[4], 256, z + ZN);         // launch 3 (bwd)

    noop_kernel<<<1, 32>>>();                                 // launch 4 (ncu alignment)

    scan_kernel<<<NBLOCKS, NTHREADS, SMEM_BYTES>>>(P, 0, 0u); // launch 5 <- ncu -s 5 target

    // layer-1 input projections: K=512 split into two K=256 halves
    gemm_k256<<<gg, 256>>>(hsf, P.w[8],        512, z);            // fwd, hsf-half
    gemm_k256<<<gg, 256>>>(hsb, P.w[8]  + 256, 512, z + ZN);       // fwd, hsb-half
    gemm_k256<<<gg, 256>>>(hsf, P.w[12],       512, z + 2 * ZN);   // bwd, hsf-half
    gemm_k256<<<gg, 256>>>(hsb, P.w[12] + 256, 512, z + 3 * ZN);   // bwd, hsb-half

    scan_kernel<<<NBLOCKS, NTHREADS, SMEM_BYTES>>>(P, 1, 8192u);
}

// round 9
// speedup vs baseline: 1.0805x; 1.0231x over previous
#include <cuda_runtime.h>
#include <cstdint>

#define TSEQ 2048
#define BATCH 64
#define HID 256
#define NTHREADS 256
#define MTOT (TSEQ * BATCH)          // 131072 rows

#define OUT_LH 67108864UL            // T*B*2H
#define LHN    65536UL               // 4*B*H

typedef unsigned long long ull;

// ---- scratch (device statics are the sanctioned no-alloc path) ----
__device__ float g_zin[4][(size_t)MTOT * 1024];   // precomputed input projections
__device__ float g_hs0f[(size_t)MTOT * HID];
__device__ float g_hs0b[(size_t)MTOT * HID];

struct Params {
    const float* __restrict__ x;
    const int*   __restrict__ len;
    const float* __restrict__ w[16];
    float*       __restrict__ out;
};

// ---------------- scan-phase shared memory layout (floats) ----------------
// sWt  : [256 k][132 rows-padded]   : 0      .. 33792   (W_hh^T, 128 rows local)
// hbuf : [2][8 b][256 k]            : 33792  .. 37888   (double-buffered h)
// zp   : [8 b][132 rows-padded]     : 37888  .. 38944
// sBias: [128]                      : 38944  .. 39072
// sLen : [8] ints                   : 39072  .. 39080
#define SM_HBUF 33792
#define SM_ZP   37888
#define SM_BIAS 38944
#define SM_LEN  39072
#define SMEM_FLOATS 39080
#define SMEM_BYTES (SMEM_FLOATS * 4)

__device__ __forceinline__ ull pck(float lo, float hi) {
    ull r;
    asm("mov.b64 %0, {%1, %2};" : "=l"(r) : "f"(lo), "f"(hi));
    return r;
}
__device__ __forceinline__ void fma2(ull& d, ull a, ull b) {
    asm("fma.rn.f32x2 %0, %1, %2, %0;" : "+l"(d) : "l"(a), "l"(b));
}
__device__ __forceinline__ float sigf(float x) {
    return __fdividef(1.f, 1.f + __expf(-x));
}
__device__ __forceinline__ uint32_t smem_u32(const void* p) {
    uint32_t a;
    asm("{ .reg .u64 t; cvta.to.shared.u64 t, %1; cvt.u32.u64 %0, t; }" : "=r"(a) : "l"(p));
    return a;
}
// DSMEM push: store v to the same smem offset in cluster rank r
__device__ __forceinline__ void st_cluster(uint32_t laddr, int rank, float v) {
    uint32_t ra;
    asm volatile("mapa.shared::cluster.u32 %0, %1, %2;" : "=r"(ra) : "r"(laddr), "r"(rank));
    asm volatile("st.shared::cluster.f32 [%0], %1;" :: "r"(ra), "f"(v) : "memory");
}
#define CLUSTER_BAR() do { \
    asm volatile("barrier.cluster.arrive.aligned;" ::: "memory"); \
    asm volatile("barrier.cluster.wait.aligned;"   ::: "memory"); } while (0)

__global__ void noop_kernel() {}

// =======================================================================
// Bulk GEMM: C[M=131072,1024] = A[M,256] @ W[1024, ldw(first 256 cols)]^T
// tile 128x128, 256 threads, 8x8 per thread via fma.rn.f32x2
// =======================================================================
__global__ void __launch_bounds__(256, 2)
gemm_k256(const float* __restrict__ A, const float* __restrict__ W, int ldw,
          float* __restrict__ C)
{
    __shared__ float sA[2][16][132];
    __shared__ float sB[2][16][132];
    const int tid = threadIdx.x;
    const int m0 = blockIdx.y << 7;
    const int n0 = blockIdx.x << 7;
    const int tx = tid & 15, ty = tid >> 4;
    const int lr = tid >> 2;               // 0..63
    const int lk = (tid & 3) << 2;         // 0,4,8,12

    const float* Ap0 = A + (size_t)(m0 + lr) * 256 + lk;
    const float* Ap1 = Ap0 + (size_t)64 * 256;
    const float* Wp0 = W + (size_t)(n0 + lr) * ldw + lk;
    const float* Wp1 = Wp0 + (size_t)64 * ldw;

    ull acc2[8][4];
#pragma unroll
    for (int i = 0; i < 8; ++i)
#pragma unroll
        for (int j = 0; j < 4; ++j) acc2[i][j] = 0ull;

    float4 ra0, ra1, rb0, rb1;

#define GLOAD(kb) do { int k0_ = (kb) << 4;                         \
        ra0 = __ldg((const float4*)(Ap0 + k0_));                    \
        ra1 = __ldg((const float4*)(Ap1 + k0_));                    \
        rb0 = __ldg((const float4*)(Wp0 + k0_));                    \
        rb1 = __ldg((const float4*)(Wp1 + k0_)); } while (0)

#define SSTORE(buf) do {                                            \
        float* a_ = &sA[buf][lk][lr];                               \
        a_[0] = ra0.x; a_[132] = ra0.y; a_[264] = ra0.z; a_[396] = ra0.w; \
        a_[64] = ra1.x; a_[196] = ra1.y; a_[328] = ra1.z; a_[460] = ra1.w; \
        float* b_ = &sB[buf][lk][lr];                               \
        b_[0] = rb0.x; b_[132] = rb0.y; b_[264] = rb0.z; b_[396] = rb0.w; \
        b_[64] = rb1.x; b_[196] = rb1.y; b_[328] = rb1.z; b_[460] = rb1.w; } while (0)

    GLOAD(0); SSTORE(0); __syncthreads();

    for (int kb = 0; kb < 16; ++kb) {
        const int cur = kb & 1;
        if (kb < 15) GLOAD(kb + 1);
#pragma unroll
        for (int k = 0; k < 16; ++k) {
            float4 a0 = *(const float4*)&sA[cur][k][ty * 8];
            float4 a1 = *(const float4*)&sA[cur][k][ty * 8 + 4];
            ulonglong2 bq0 = *(const ulonglong2*)&sB[cur][k][tx * 8];
            ulonglong2 bq1 = *(const ulonglong2*)&sB[cur][k][tx * 8 + 4];
            float am[8] = {a0.x, a0.y, a0.z, a0.w, a1.x, a1.y, a1.z, a1.w};
#pragma unroll
            for (int i = 0; i < 8; ++i) {
                ull ap = pck(am[i], am[i]);
                fma2(acc2[i][0], ap, bq0.x);
                fma2(acc2[i][1], ap, bq0.y);
                fma2(acc2[i][2], ap, bq1.x);
                fma2(acc2[i][3], ap, bq1.y);
            }
        }
        if (kb < 15) { SSTORE(cur ^ 1); __syncthreads(); }
    }

#pragma unroll
    for (int i = 0; i < 8; ++i) {
        size_t row = (size_t)(m0 + ty * 8 + i);
        ulonglong2 o0; o0.x = acc2[i][0]; o0.y = acc2[i][1];
        ulonglong2 o1; o1.x = acc2[i][2]; o1.y = acc2[i][3];
        *(ulonglong2*)(C + row * 1024 + n0 + tx * 8)     = o0;
        *(ulonglong2*)(C + row * 1024 + n0 + tx * 8 + 4) = o1;
    }
}

// =======================================================================
// Persistent recurrent scan — cluster version.
// Grid 128, cluster 8. dir = blk>>6; batch-group bg = (blk>>3)&7 (8 batches);
// unit-group ug = blk&7 (32 hidden units, 128 gate rows).
// The 8 CTAs of a cluster share one batch-group: h is exchanged via DSMEM
// push + barrier.cluster — NO global-memory sync on the critical path.
// GEMM thread: 4 gate rows x 1 batch x full K=256 (fma.rn.f32x2 row pairs).
// Update thread: 1 unit x 1 batch, cell state in register.
// =======================================================================
__global__ void __launch_bounds__(NTHREADS, 1) __cluster_dims__(8, 1, 1)
scan_kernel(Params p, int layer)
{
    extern __shared__ float sm[];
    float* sWt   = sm;                    // [k][132] (128 local rows)
    float* hbuf  = sm + SM_HBUF;          // [2][8][256]
    float* zp    = sm + SM_ZP;            // [8][132]
    float* sBias = sm + SM_BIAS;          // [128]
    int*   sLen  = (int*)(sm + SM_LEN);   // [8]

    const int tid = threadIdx.x;
    const int dir = blockIdx.x >> 6;
    const int bg  = (blockIdx.x >> 3) & 7;
    const int ug  = blockIdx.x & 7;
    const int j0a = ug << 5;              // absolute unit base (32 units)
    const int bl  = tid >> 5;             // local batch 0..7
    const int r4  = tid & 31;             // gemm row-group / update unit
    const int gb  = (bg << 3) + bl;       // global batch

    if (tid < 8) sLen[tid] = p.len[(bg << 3) + tid];

    const float* whh = p.w[layer * 8 + dir * 4 + 1];
    const float* bih = p.w[layer * 8 + dir * 4 + 2];
    const float* bhh = p.w[layer * 8 + dir * 4 + 3];

    // W_hh^T into smem: local row lr = gate*32 + u -> global row gate*256 + j0a + u
    for (int idx = tid; idx < 128 * 256; idx += NTHREADS) {
        int lr = idx >> 8, k = idx & 255;
        int grow = ((lr >> 5) << 8) + j0a + (lr & 31);
        sWt[k * 132 + lr] = whh[(size_t)grow * HID + k];
    }
    if (tid < 128) {
        int grow = ((tid >> 5) << 8) + j0a + (tid & 31);
        sBias[tid] = bih[grow] + bhh[grow];
    }
    // zero h(0) (own full copy)
    for (int i = tid; i < 8 * 256; i += NTHREADS) hbuf[i] = 0.f;
    float creg = 0.f;
    __syncthreads();

    const int myLen = sLen[bl];
    const float4 bq = *(const float4*)&sBias[r4 * 4];

    // zin sources + per-example time modes (0: t, 1: (t+len)%T, 2: (t+T-len)%T)
    const float *zsA, *zsB = nullptr;
    int mA, mB = 0;
    if (layer == 0)      { zsA = g_zin[dir]; mA = dir ? 1 : 0; }
    else if (dir == 0)   { zsA = g_zin[0]; mA = 0; zsB = g_zin[1]; mB = 2; }
    else                 { zsA = g_zin[2]; mA = 1; zsB = g_zin[3]; mB = 0; }
    const int zc = ((r4 >> 3) << 8) + j0a + ((r4 & 7) << 2);   // gate*256 + unit

    auto zg1 = [&](const float* src, int mode, int s) -> float4 {
        int t = dir ? (TSEQ - 1 - s) : s;
        if (mode == 1) t += myLen;
        else if (mode == 2) t += TSEQ - myLen;
        if (t >= TSEQ) t -= TSEQ;
        return __ldg((const float4*)(src + ((size_t)t * BATCH + gb) * 1024 + zc));
    };

    float4 zAc = zg1(zsA, mA, 0);
    float4 zBc = zsB ? zg1(zsB, mB, 0) : make_float4(0.f, 0.f, 0.f, 0.f);

    const uint32_t xaddr = smem_u32(&hbuf[bl * 256 + j0a + r4]);  // exchange slot (parity 0 base)
    float* hs0 = dir ? g_hs0b : g_hs0f;

    for (int s = 0; s < TSEQ; ++s) {
        const int par = s & 1;
        const int t = dir ? (TSEQ - 1 - s) : s;

        float4 zA = zAc, zB = zBc;
        if (s + 1 < TSEQ) {
            zAc = zg1(zsA, mA, s + 1);
            if (zsB) zBc = zg1(zsB, mB, s + 1);
        }

        // ---- recurrent GEMM: 4 rows (2 packed pairs) x 1 batch x K=256 ----
        ull aLo = pck(zA.x + zB.x + bq.x, zA.y + zB.y + bq.y);
        ull aHi = pck(zA.z + zB.z + bq.z, zA.w + zB.w + bq.w);
        {
            const float* hrow = hbuf + par * 2048 + bl * 256;
            const float* wcol = sWt + r4 * 4;
#pragma unroll 8
            for (int k4 = 0; k4 < 64; ++k4) {
                float4 hq = *(const float4*)(hrow + k4 * 4);
                ulonglong2 w0 = *(const ulonglong2*)(wcol + (k4 * 4 + 0) * 132);
                ulonglong2 w1 = *(const ulonglong2*)(wcol + (k4 * 4 + 1) * 132);
                ulonglong2 w2 = *(const ulonglong2*)(wcol + (k4 * 4 + 2) * 132);
                ulonglong2 w3 = *(const ulonglong2*)(wcol + (k4 * 4 + 3) * 132);
                ull h0 = pck(hq.x, hq.x), h1 = pck(hq.y, hq.y);
                ull h2 = pck(hq.z, hq.z), h3 = pck(hq.w, hq.w);
                fma2(aLo, w0.x, h0); fma2(aHi, w0.y, h0);
                fma2(aLo, w1.x, h1); fma2(aHi, w1.y, h1);
                fma2(aLo, w2.x, h2); fma2(aHi, w2.y, h2);
                fma2(aLo, w3.x, h3); fma2(aHi, w3.y, h3);
            }
        }
        {
            ulonglong2 o; o.x = aLo; o.y = aHi;
            *(ulonglong2*)&zp[bl * 132 + r4 * 4] = o;
        }
        __syncthreads();

        // ---- cell update: thread owns (unit r4, batch bl) ----
        {
            const float* zr = zp + bl * 132;
            float zi = zr[0  + r4], zf = zr[32 + r4];
            float zg = zr[64 + r4], zo = zr[96 + r4];
            float ig = sigf(zi), fg = sigf(zf), gg = tanhf(zg), og = sigf(zo);
            creg = fg * creg + ig * gg;
            float h = og * tanhf(creg);

            bool trig = dir ? (t == TSEQ - myLen) : (t == myLen - 1);
            if (trig) {   // final valid state for this example
                size_t o = OUT_LH + ((size_t)(layer * 2 + dir) * BATCH + gb) * HID + j0a + r4;
                p.out[o] = h;
                p.out[o + LHN] = creg;
            }
            if (layer == 0) {
                hs0[((size_t)t * BATCH + gb) * HID + j0a + r4] = h;
            } else {
                int tm = t, col = j0a + r4;
                if (dir) { tm = t + myLen; if (tm >= TSEQ) tm -= TSEQ; col += HID; }
                p.out[((size_t)tm * BATCH + gb) * (2 * HID) + col] = (tm < myLen) ? h : 0.f;
            }

            // ---- DSMEM exchange: push h to all 8 cluster ranks (incl. self) ----
            uint32_t la = xaddr + (unsigned)((par ^ 1) * 2048) * 4u;
#pragma unroll
            for (int r = 0; r < 8; ++r) st_cluster(la, r, h);
        }

        CLUSTER_BAR();   // DSMEM writes visible cluster-wide; also syncs the CTA
    }
}

extern "C" void kernel_launch(void* const* d_in, const int* in_sizes, int n_in,
                              void* d_out, int out_size) {
    Params P;
    P.x   = (const float*)d_in[0];
    P.len = (const int*)d_in[1];
    for (int i = 0; i < 16; ++i) P.w[i] = (const float*)d_in[2 + i];
    P.out = (float*)d_out;

    void *zp_, *hsf_, *hsb_;
    cudaGetSymbolAddress(&zp_,  g_zin);
    cudaGetSymbolAddress(&hsf_, g_hs0f);
    cudaGetSymbolAddress(&hsb_, g_hs0b);
    float* z = (float*)zp_;
    const float* hsf = (const float*)hsf_;
    const float* hsb = (const float*)hsb_;
    const size_t ZN = (size_t)MTOT * 1024;

    cudaFuncSetAttribute(scan_kernel, cudaFuncAttributeMaxDynamicSharedMemorySize, SMEM_BYTES);

    dim3 gg(8, 1024);   // N-tiles x M-tiles

    // layer-0 input projections (K=256)
    gemm_k256<<<gg, 256>>>(P.x, P.w[0], 256, z);              // launch 1 (fwd)
    gemm_k256<<<gg, 256>>>(P.x, P.w[4], 256, z + ZN);         // launch 2 (bwd)

    noop_kernel<<<1, 32>>>();                                 // launch 3 (ncu alignment)
    noop_kernel<<<1, 32>>>();                                 // launch 4

    scan_kernel<<<128, NTHREADS, SMEM_BYTES>>>(P, 0);         // launch 5 <- ncu -s 5 target

    // layer-1 input projections: K=512 split into two K=256 halves
    gemm_k256<<<gg, 256>>>(hsf, P.w[8],        512, z);            // fwd, hsf-half
    gemm_k256<<<gg, 256>>>(hsb, P.w[8]  + 256, 512, z + ZN);       // fwd, hsb-half
    gemm_k256<<<gg, 256>>>(hsf, P.w[12],       512, z + 2 * ZN);   // bwd, hsf-half
    gemm_k256<<<gg, 256>>>(hsb, P.w[12] + 256, 512, z + 3 * ZN);   // bwd, hsb-half

    scan_kernel<<<128, NTHREADS, SMEM_BYTES>>>(P, 1);
}

// round 11
// speedup vs baseline: 1.2615x; 1.1676x over previous
#include <cuda_runtime.h>
#include <cstdint>

#define TSEQ 2048
#define BATCH 64
#define HID 256
#define NTHREADS 256
#define MTOT (TSEQ * BATCH)          // 131072 rows

#define OUT_LH 67108864UL            // T*B*2H
#define LHN    65536UL               // 4*B*H

typedef unsigned long long ull;

// ---- scratch (device statics are the sanctioned no-alloc path) ----
__device__ float g_zin[4][(size_t)MTOT * 1024];   // precomputed input projections
__device__ float g_hs0f[(size_t)MTOT * HID];
__device__ float g_hs0b[(size_t)MTOT * HID];

struct Params {
    const float* __restrict__ x;
    const int*   __restrict__ len;
    const float* __restrict__ w[16];
    float*       __restrict__ out;
};

// ---------------- scan-phase shared memory layout (floats) ----------------
// hbuf : [2 par][256 k][8 b]      : 0     .. 4096
// zp   : [8 chunk][128 row][10]   : 4096  .. 14336  (z partial sums)
// sBias: [128]                    : 14336 .. 14464
// sLen : [8] ints                 : 14464 .. 14472
#define SM_ZP   4096
#define SM_BIAS 14336
#define SM_LEN  14464
#define SMEM_FLOATS 14472
#define SMEM_BYTES (SMEM_FLOATS * 4)

__device__ __forceinline__ ull pck(float lo, float hi) {
    ull r;
    asm("mov.b64 %0, {%1, %2};" : "=l"(r) : "f"(lo), "f"(hi));
    return r;
}
__device__ __forceinline__ void fma2(ull& d, ull a, ull b) {
    asm("fma.rn.f32x2 %0, %1, %2, %0;" : "+l"(d) : "l"(a), "l"(b));
}
__device__ __forceinline__ float sigf(float x) {
    return __fdividef(1.f, 1.f + __expf(-x));
}
__device__ __forceinline__ uint32_t smem_u32(const void* p) {
    uint32_t a;
    asm("{ .reg .u64 t; cvta.to.shared.u64 t, %1; cvt.u32.u64 %0, t; }" : "=r"(a) : "l"(p));
    return a;
}
#define CLUSTER_BAR() do { \
    asm volatile("barrier.cluster.arrive.aligned;" ::: "memory"); \
    asm volatile("barrier.cluster.wait.aligned;"   ::: "memory"); } while (0)

__global__ void noop_kernel() {}

// =======================================================================
// Bulk GEMM: C[M=131072,1024] = A[M,256] @ W[1024, ldw(first 256 cols)]^T
// tile 128x128, 256 threads, 8x8 per thread via fma.rn.f32x2
// =======================================================================
__global__ void __launch_bounds__(256, 2)
gemm_k256(const float* __restrict__ A, const float* __restrict__ W, int ldw,
          float* __restrict__ C)
{
    __shared__ float sA[2][16][132];
    __shared__ float sB[2][16][132];
    const int tid = threadIdx.x;
    const int m0 = blockIdx.y << 7;
    const int n0 = blockIdx.x << 7;
    const int tx = tid & 15, ty = tid >> 4;
    const int lr = tid >> 2;               // 0..63
    const int lk = (tid & 3) << 2;         // 0,4,8,12

    const float* Ap0 = A + (size_t)(m0 + lr) * 256 + lk;
    const float* Ap1 = Ap0 + (size_t)64 * 256;
    const float* Wp0 = W + (size_t)(n0 + lr) * ldw + lk;
    const float* Wp1 = Wp0 + (size_t)64 * ldw;

    ull acc2[8][4];
#pragma unroll
    for (int i = 0; i < 8; ++i)
#pragma unroll
        for (int j = 0; j < 4; ++j) acc2[i][j] = 0ull;

    float4 ra0, ra1, rb0, rb1;

#define GLOAD(kb) do { int k0_ = (kb) << 4;                         \
        ra0 = __ldg((const float4*)(Ap0 + k0_));                    \
        ra1 = __ldg((const float4*)(Ap1 + k0_));                    \
        rb0 = __ldg((const float4*)(Wp0 + k0_));                    \
        rb1 = __ldg((const float4*)(Wp1 + k0_)); } while (0)

#define SSTORE(buf) do {                                            \
        float* a_ = &sA[buf][lk][lr];                               \
        a_[0] = ra0.x; a_[132] = ra0.y; a_[264] = ra0.z; a_[396] = ra0.w; \
        a_[64] = ra1.x; a_[196] = ra1.y; a_[328] = ra1.z; a_[460] = ra1.w; \
        float* b_ = &sB[buf][lk][lr];                               \
        b_[0] = rb0.x; b_[132] = rb0.y; b_[264] = rb0.z; b_[396] = rb0.w; \
        b_[64] = rb1.x; b_[196] = rb1.y; b_[328] = rb1.z; b_[460] = rb1.w; } while (0)

    GLOAD(0); SSTORE(0); __syncthreads();

    for (int kb = 0; kb < 16; ++kb) {
        const int cur = kb & 1;
        if (kb < 15) GLOAD(kb + 1);
#pragma unroll
        for (int k = 0; k < 16; ++k) {
            float4 a0 = *(const float4*)&sA[cur][k][ty * 8];
            float4 a1 = *(const float4*)&sA[cur][k][ty * 8 + 4];
            ulonglong2 bq0 = *(const ulonglong2*)&sB[cur][k][tx * 8];
            ulonglong2 bq1 = *(const ulonglong2*)&sB[cur][k][tx * 8 + 4];
            float am[8] = {a0.x, a0.y, a0.z, a0.w, a1.x, a1.y, a1.z, a1.w};
#pragma unroll
            for (int i = 0; i < 8; ++i) {
                ull ap = pck(am[i], am[i]);
                fma2(acc2[i][0], ap, bq0.x);
                fma2(acc2[i][1], ap, bq0.y);
                fma2(acc2[i][2], ap, bq1.x);
                fma2(acc2[i][3], ap, bq1.y);
            }
        }
        if (kb < 15) { SSTORE(cur ^ 1); __syncthreads(); }
    }

#pragma unroll
    for (int i = 0; i < 8; ++i) {
        size_t row = (size_t)(m0 + ty * 8 + i);
        ulonglong2 o0; o0.x = acc2[i][0]; o0.y = acc2[i][1];
        ulonglong2 o1; o1.x = acc2[i][2]; o1.y = acc2[i][3];
        *(ulonglong2*)(C + row * 1024 + n0 + tx * 8)     = o0;
        *(ulonglong2*)(C + row * 1024 + n0 + tx * 8 + 4) = o1;
    }
}

// =======================================================================
// Persistent recurrent scan — cluster + register-resident weights.
// Grid 128, cluster 8. dir = blk>>6; bg = (blk>>3)&7 (8 batches);
// ug = blk&7 (32 hidden units = 128 gate rows).
// GEMM role: warp = k-chunk (32 k), lane = 4-row group. W_hh lives in
// 128 registers/thread; h reads are warp-broadcast LDS. Partial z reduced
// across the 8 k-chunk warps through smem.
// Update role: warp = batch, lane = unit; cell state in register.
// h exchanged via DSMEM push + barrier.cluster (no global-mem sync).
// =======================================================================
__global__ void __launch_bounds__(NTHREADS, 1) __cluster_dims__(8, 1, 1)
scan_kernel(Params p, int layer)
{
    extern __shared__ float sm[];
    float* hbuf  = sm;                    // [2][256][8]
    float* zp    = sm + SM_ZP;            // [8][128][10]
    float* sBias = sm + SM_BIAS;          // [128]
    int*   sLen  = (int*)(sm + SM_LEN);   // [8]

    const int tid = threadIdx.x;
    const int dir = blockIdx.x >> 6;
    const int bg  = (blockIdx.x >> 3) & 7;
    const int ug  = blockIdx.x & 7;
    const int j0a = ug << 5;              // absolute unit base (32 units)
    // GEMM roles
    const int chunk = tid >> 5;           // k-chunk (warp)
    const int rg    = tid & 31;           // 4-row group (lane)
    // update roles
    const int ub = tid >> 5;              // local batch (warp)
    const int uu = tid & 31;              // unit (lane)
    const int gb = (bg << 3) + ub;        // global batch

    if (tid < 8) sLen[tid] = p.len[(bg << 3) + tid];

    const float* whh = p.w[layer * 8 + dir * 4 + 1];
    const float* bih = p.w[layer * 8 + dir * 4 + 2];
    const float* bhh = p.w[layer * 8 + dir * 4 + 3];

    // ---- W_hh into registers: 4 rows x 32 k = 32 float4 ----
    float4 wq[4][8];
    {
        const int g  = rg >> 3;
        const int u0 = (rg & 7) << 2;
#pragma unroll
        for (int i = 0; i < 4; ++i) {
            const float* wr = whh + (size_t)((g << 8) + j0a + u0 + i) * HID + (chunk << 5);
#pragma unroll
            for (int q = 0; q < 8; ++q)
                wq[i][q] = __ldg((const float4*)(wr + q * 4));
        }
    }
    if (tid < 128) {
        int grow = ((tid >> 5) << 8) + j0a + (tid & 31);
        sBias[tid] = bih[grow] + bhh[grow];
    }
    for (int i = tid; i < 4096; i += NTHREADS) hbuf[i] = 0.f;
    float creg = 0.f;
    __syncthreads();

    const int myLen = sLen[ub];

    // zin sources + per-example time modes (0: t, 1: (t+len)%T, 2: (t+T-len)%T)
    const float *zsA, *zsB = nullptr;
    int mA, mB = 0;
    if (layer == 0)      { zsA = g_zin[dir]; mA = dir ? 1 : 0; }
    else if (dir == 0)   { zsA = g_zin[0]; mA = 0; zsB = g_zin[1]; mB = 2; }
    else                 { zsA = g_zin[2]; mA = 1; zsB = g_zin[3]; mB = 0; }

    auto tfix = [&](int mode, int s) -> int {
        int t = dir ? (TSEQ - 1 - s) : s;
        if (mode == 1) t += myLen;
        else if (mode == 2) t += TSEQ - myLen;
        if (t >= TSEQ) t -= TSEQ;
        return t;
    };

    // prime z prefetch (update threads: 4 scalar gathers per source, coalesced)
    float zA[4], zB[4];
    {
        size_t rA = (size_t)tfix(mA, 0) * BATCH + gb;
#pragma unroll
        for (int g = 0; g < 4; ++g) zA[g] = __ldg(zsA + rA * 1024 + (g << 8) + j0a + uu);
        if (zsB) {
            size_t rB = (size_t)tfix(mB, 0) * BATCH + gb;
#pragma unroll
            for (int g = 0; g < 4; ++g) zB[g] = __ldg(zsB + rB * 1024 + (g << 8) + j0a + uu);
        } else { zB[0] = zB[1] = zB[2] = zB[3] = 0.f; }
    }

    // DSMEM exchange addresses: this thread's h slot on each cluster rank (parity 0)
    uint32_t ra[8];
    {
        uint32_t base = smem_u32(hbuf) + (uint32_t)(((j0a + uu) << 3) + ub) * 4u;
#pragma unroll
        for (int r = 0; r < 8; ++r)
            asm("mapa.shared::cluster.u32 %0, %1, %2;" : "=r"(ra[r]) : "r"(base), "r"(r));
    }
    float* hs0 = dir ? g_hs0b : g_hs0f;

    CLUSTER_BAR();   // all CTAs initialized before any DSMEM pushes

    for (int s = 0; s < TSEQ; ++s) {
        const int par = s & 1;
        const int t = dir ? (TSEQ - 1 - s) : s;

        float zcA[4], zcB[4];
#pragma unroll
        for (int g = 0; g < 4; ++g) { zcA[g] = zA[g]; zcB[g] = zB[g]; }
        if (s + 1 < TSEQ) {   // prefetch next step's z (addresses independent of h)
            size_t rA = (size_t)tfix(mA, s + 1) * BATCH + gb;
#pragma unroll
            for (int g = 0; g < 4; ++g) zA[g] = __ldg(zsA + rA * 1024 + (g << 8) + j0a + uu);
            if (zsB) {
                size_t rB = (size_t)tfix(mB, s + 1) * BATCH + gb;
#pragma unroll
                for (int g = 0; g < 4; ++g) zB[g] = __ldg(zsB + rB * 1024 + (g << 8) + j0a + uu);
            }
        }

        // ---- recurrent GEMM: reg-resident W, broadcast h, 4 rows x 8 batches ----
        ull acc[4][4];
#pragma unroll
        for (int i = 0; i < 4; ++i)
#pragma unroll
            for (int j = 0; j < 4; ++j) acc[i][j] = 0ull;
        {
            const float* hrow = hbuf + par * 2048 + (chunk << 8);
#pragma unroll
            for (int q = 0; q < 8; ++q) {
#pragma unroll
                for (int j = 0; j < 4; ++j) {
                    const float* hk = hrow + ((q << 2) + j) * 8;
                    ulonglong2 hp  = *(const ulonglong2*)hk;        // batches 0-3
                    ulonglong2 hp2 = *(const ulonglong2*)(hk + 4);  // batches 4-7
                    const float w0f = ((const float*)&wq[0][q])[j];
                    const float w1f = ((const float*)&wq[1][q])[j];
                    const float w2f = ((const float*)&wq[2][q])[j];
                    const float w3f = ((const float*)&wq[3][q])[j];
                    ull w0 = pck(w0f, w0f), w1 = pck(w1f, w1f);
                    ull w2 = pck(w2f, w2f), w3 = pck(w3f, w3f);
                    fma2(acc[0][0], hp.x,  w0); fma2(acc[0][1], hp.y,  w0);
                    fma2(acc[0][2], hp2.x, w0); fma2(acc[0][3], hp2.y, w0);
                    fma2(acc[1][0], hp.x,  w1); fma2(acc[1][1], hp.y,  w1);
                    fma2(acc[1][2], hp2.x, w1); fma2(acc[1][3], hp2.y, w1);
                    fma2(acc[2][0], hp.x,  w2); fma2(acc[2][1], hp.y,  w2);
                    fma2(acc[2][2], hp2.x, w2); fma2(acc[2][3], hp2.y, w2);
                    fma2(acc[3][0], hp.x,  w3); fma2(acc[3][1], hp.y,  w3);
                    fma2(acc[3][2], hp2.x, w3); fma2(acc[3][3], hp2.y, w3);
                }
            }
        }
        // store z partials: zp[chunk][row][batch-pair]
        {
            float* zr = zp + chunk * 1280 + (rg << 2) * 10;
#pragma unroll
            for (int i = 0; i < 4; ++i)
#pragma unroll
                for (int bp = 0; bp < 4; ++bp)
                    *(ull*)(zr + i * 10 + bp * 2) = acc[i][bp];
        }
        __syncthreads();

        // ---- reduce + cell update: thread owns (unit uu, batch ub) ----
        {
            float zg4[4];
#pragma unroll
            for (int g = 0; g < 4; ++g) {
                int row = (g << 5) + uu;
                float v = zcA[g] + zcB[g] + sBias[row];
                const float* zpr = zp + row * 10 + ub;
#pragma unroll
                for (int c = 0; c < 8; ++c) v += zpr[c * 1280];
                zg4[g] = v;
            }
            float ig = sigf(zg4[0]), fg = sigf(zg4[1]);
            float gg = tanhf(zg4[2]), og = sigf(zg4[3]);
            creg = fg * creg + ig * gg;
            float h = og * tanhf(creg);

            bool trig = dir ? (t == TSEQ - myLen) : (t == myLen - 1);
            if (trig) {   // final valid state for this example
                size_t o = OUT_LH + ((size_t)(layer * 2 + dir) * BATCH + gb) * HID + j0a + uu;
                p.out[o] = h;
                p.out[o + LHN] = creg;
            }
            if (layer == 0) {
                hs0[((size_t)t * BATCH + gb) * HID + j0a + uu] = h;
            } else {
                int tm = t, col = j0a + uu;
                if (dir) { tm = t + myLen; if (tm >= TSEQ) tm -= TSEQ; col += HID; }
                p.out[((size_t)tm * BATCH + gb) * (2 * HID) + col] = (tm < myLen) ? h : 0.f;
            }

            // ---- DSMEM exchange: push h to all 8 cluster ranks ----
            uint32_t off = (uint32_t)((par ^ 1) << 13);   // 8192 bytes per parity
#pragma unroll
            for (int r = 0; r < 8; ++r) {
                uint32_t ad = ra[r] + off;
                asm volatile("st.shared::cluster.f32 [%0], %1;" :: "r"(ad), "f"(h) : "memory");
            }
        }

        CLUSTER_BAR();   // DSMEM h visible cluster-wide; also orders zp reuse
    }
}

extern "C" void kernel_launch(void* const* d_in, const int* in_sizes, int n_in,
                              void* d_out, int out_size) {
    Params P;
    P.x   = (const float*)d_in[0];
    P.len = (const int*)d_in[1];
    for (int i = 0; i < 16; ++i) P.w[i] = (const float*)d_in[2 + i];
    P.out = (float*)d_out;

    void *zp_, *hsf_, *hsb_;
    cudaGetSymbolAddress(&zp_,  g_zin);
    cudaGetSymbolAddress(&hsf_, g_hs0f);
    cudaGetSymbolAddress(&hsb_, g_hs0b);
    float* z = (float*)zp_;
    const float* hsf = (const float*)hsf_;
    const float* hsb = (const float*)hsb_;
    const size_t ZN = (size_t)MTOT * 1024;

    cudaFuncSetAttribute(scan_kernel, cudaFuncAttributeMaxDynamicSharedMemorySize, SMEM_BYTES);

    dim3 gg(8, 1024);   // N-tiles x M-tiles

    // layer-0 input projections (K=256)
    gemm_k256<<<gg, 256>>>(P.x, P.w[0], 256, z);              // kernel 1 (fwd)
    gemm_k256<<<gg, 256>>>(P.x, P.w[4], 256, z + ZN);         // kernel 2 (bwd)

    noop_kernel<<<1, 32>>>();                                 // kernel 3 (ncu alignment)

    scan_kernel<<<128, NTHREADS, SMEM_BYTES>>>(P, 0);         // kernel 4 <- ncu target

    // layer-1 input projections: K=512 split into two K=256 halves
    gemm_k256<<<gg, 256>>>(hsf, P.w[8],        512, z);            // fwd, hsf-half
    gemm_k256<<<gg, 256>>>(hsb, P.w[8]  + 256, 512, z + ZN);       // fwd, hsb-half
    gemm_k256<<<gg, 256>>>(hsf, P.w[12],       512, z + 2 * ZN);   // bwd, hsf-half
    gemm_k256<<<gg, 256>>>(hsb, P.w[12] + 256, 512, z + 3 * ZN);   // bwd, hsb-half

    scan_kernel<<<128, NTHREADS, SMEM_BYTES>>>(P, 1);
}

// round 14
// speedup vs baseline: 2.1025x; 1.6667x over previous
#include <cuda_runtime.h>
#include <cstdint>

#define TSEQ 2048
#define BATCH 64
#define HID 256
#define NTHREADS 256
#define MTOT (TSEQ * BATCH)          // 131072 rows

#define OUT_LH 67108864UL            // T*B*2H
#define LHN    65536UL               // 4*B*H

typedef unsigned long long ull;

// ---- scratch (device statics are the sanctioned no-alloc path) ----
__device__ float g_zin[4][(size_t)MTOT * 1024];   // precomputed input projections
__device__ float g_hs0f[(size_t)MTOT * HID];
__device__ float g_hs0b[(size_t)MTOT * HID];

struct Params {
    const float* __restrict__ x;
    const int*   __restrict__ len;
    const float* __restrict__ w[16];
    float*       __restrict__ out;
};

// ---------------- scan-phase shared memory layout (floats) ----------------
// hbuf : [2 par][256 k][8 b]      : 0     .. 4096   (full h, double-buffered)
// zp   : [8 chunk][64 row][10]    : 4096  .. 9216   (z partial sums; EVEN stride
//                                                    so 8-byte stores stay aligned)
// sBias: [64]                     : 9216  .. 9280
// sLen : [8] ints                 : 9280  .. 9288
#define SM_ZP   4096
#define SM_BIAS 9216
#define SM_LEN  9280
#define SMEM_FLOATS 9288
#define SMEM_BYTES (SMEM_FLOATS * 4)

__device__ __forceinline__ ull pck(float lo, float hi) {
    ull r;
    asm("mov.b64 %0, {%1, %2};" : "=l"(r) : "f"(lo), "f"(hi));
    return r;
}
__device__ __forceinline__ void fma2(ull& d, ull a, ull b) {
    asm("fma.rn.f32x2 %0, %1, %2, %0;" : "+l"(d) : "l"(a), "l"(b));
}
__device__ __forceinline__ float sigf(float x) {
    return __fdividef(1.f, 1.f + __expf(-x));
}
__device__ __forceinline__ uint32_t smem_u32(const void* p) {
    uint32_t a;
    asm("{ .reg .u64 t; cvta.to.shared.u64 t, %1; cvt.u32.u64 %0, t; }" : "=r"(a) : "l"(p));
    return a;
}
#define CLUSTER_BAR() do { \
    asm volatile("barrier.cluster.arrive.aligned;" ::: "memory"); \
    asm volatile("barrier.cluster.wait.aligned;"   ::: "memory"); } while (0)

__global__ void noop_kernel() {}

// =======================================================================
// Bulk GEMM: C[M=131072,1024] = A[M,256] @ W[1024, ldw(first 256 cols)]^T
// tile 128x128, 256 threads, 8x8 per thread via fma.rn.f32x2
// =======================================================================
__global__ void __launch_bounds__(256, 2)
gemm_k256(const float* __restrict__ A, const float* __restrict__ W, int ldw,
          float* __restrict__ C)
{
    __shared__ float sA[2][16][132];
    __shared__ float sB[2][16][132];
    const int tid = threadIdx.x;
    const int m0 = blockIdx.y << 7;
    const int n0 = blockIdx.x << 7;
    const int tx = tid & 15, ty = tid >> 4;
    const int lr = tid >> 2;               // 0..63
    const int lk = (tid & 3) << 2;         // 0,4,8,12

    const float* Ap0 = A + (size_t)(m0 + lr) * 256 + lk;
    const float* Ap1 = Ap0 + (size_t)64 * 256;
    const float* Wp0 = W + (size_t)(n0 + lr) * ldw + lk;
    const float* Wp1 = Wp0 + (size_t)64 * ldw;

    ull acc2[8][4];
#pragma unroll
    for (int i = 0; i < 8; ++i)
#pragma unroll
        for (int j = 0; j < 4; ++j) acc2[i][j] = 0ull;

    float4 ra0, ra1, rb0, rb1;

#define GLOAD(kb) do { int k0_ = (kb) << 4;                         \
        ra0 = __ldg((const float4*)(Ap0 + k0_));                    \
        ra1 = __ldg((const float4*)(Ap1 + k0_));                    \
        rb0 = __ldg((const float4*)(Wp0 + k0_));                    \
        rb1 = __ldg((const float4*)(Wp1 + k0_)); } while (0)

#define SSTORE(buf) do {                                            \
        float* a_ = &sA[buf][lk][lr];                               \
        a_[0] = ra0.x; a_[132] = ra0.y; a_[264] = ra0.z; a_[396] = ra0.w; \
        a_[64] = ra1.x; a_[196] = ra1.y; a_[328] = ra1.z; a_[460] = ra1.w; \
        float* b_ = &sB[buf][lk][lr];                               \
        b_[0] = rb0.x; b_[132] = rb0.y; b_[264] = rb0.z; b_[396] = rb0.w; \
        b_[64] = rb1.x; b_[196] = rb1.y; b_[328] = rb1.z; b_[460] = rb1.w; } while (0)

    GLOAD(0); SSTORE(0); __syncthreads();

    for (int kb = 0; kb < 16; ++kb) {
        const int cur = kb & 1;
        if (kb < 15) GLOAD(kb + 1);
#pragma unroll
        for (int k = 0; k < 16; ++k) {
            float4 a0 = *(const float4*)&sA[cur][k][ty * 8];
            float4 a1 = *(const float4*)&sA[cur][k][ty * 8 + 4];
            ulonglong2 bq0 = *(const ulonglong2*)&sB[cur][k][tx * 8];
            ulonglong2 bq1 = *(const ulonglong2*)&sB[cur][k][tx * 8 + 4];
            float am[8] = {a0.x, a0.y, a0.z, a0.w, a1.x, a1.y, a1.z, a1.w};
#pragma unroll
            for (int i = 0; i < 8; ++i) {
                ull ap = pck(am[i], am[i]);
                fma2(acc2[i][0], ap, bq0.x);
                fma2(acc2[i][1], ap, bq0.y);
                fma2(acc2[i][2], ap, bq1.x);
                fma2(acc2[i][3], ap, bq1.y);
            }
        }
        if (kb < 15) { SSTORE(cur ^ 1); __syncthreads(); }
    }

#pragma unroll
    for (int i = 0; i < 8; ++i) {
        size_t row = (size_t)(m0 + ty * 8 + i);
        ulonglong2 o0; o0.x = acc2[i][0]; o0.y = acc2[i][1];
        ulonglong2 o1; o1.x = acc2[i][2]; o1.y = acc2[i][3];
        *(ulonglong2*)(C + row * 1024 + n0 + tx * 8)     = o0;
        *(ulonglong2*)(C + row * 1024 + n0 + tx * 8 + 4) = o1;
    }
}

// =======================================================================
// Persistent recurrent scan — 16-CTA cluster, occupancy-2 for latency
// overlap between independent clusters.
// Grid 256: dir = bid>>7; bg = (bid>>4)&7 (8 batches); ug = bid&15 (16
// units = 64 gate rows). Cluster 16 spans all units of one (dir,bg).
// GEMM role: warp = k-chunk (32 k), lane = 2-row group; W_hh in 64 regs;
// h reads warp-broadcast LDS; partials reduced via smem.
// Update role (tid<128): warp-half = batch, lane = unit.
// Exchange: STS own h block, then 16B DSMEM pushes to 15 peers.
// =======================================================================
__global__ void __launch_bounds__(NTHREADS, 2) __cluster_dims__(16, 1, 1)
scan_kernel(Params p, int layer)
{
    extern __shared__ float sm[];
    float* hbuf  = sm;                    // [2][256][8]
    float* zp    = sm + SM_ZP;            // [8][64][10]
    float* sBias = sm + SM_BIAS;          // [64]
    int*   sLen  = (int*)(sm + SM_LEN);   // [8]

    const int tid = threadIdx.x;
    const int bid = blockIdx.x;
    const int dir = bid >> 7;
    const int bg  = (bid >> 4) & 7;
    const int ug  = bid & 15;             // == cluster rank
    const int j0a = ug << 4;              // absolute unit base (16 units)
    // GEMM roles
    const int chunk = tid >> 5;           // k-chunk (warp)
    const int rg    = tid & 31;           // 2-row group (lane)
    // update roles (tid < 128)
    const int ub = tid >> 4;              // local batch 0..7
    const int uu = tid & 15;              // unit 0..15
    const int gb = (bg << 3) + ub;        // global batch

    if (tid < 8) sLen[tid] = p.len[(bg << 3) + tid];

    const float* whh = p.w[layer * 8 + dir * 4 + 1];
    const float* bih = p.w[layer * 8 + dir * 4 + 2];
    const float* bhh = p.w[layer * 8 + dir * 4 + 3];

    // ---- W_hh into registers: 2 rows x 32 k = 16 float4 ----
    float4 wq[2][8];
#pragma unroll
    for (int i = 0; i < 2; ++i) {
        int lr = rg * 2 + i;                       // local row 0..63 = gate*16+unit
        int grow = ((lr >> 4) << 8) + j0a + (lr & 15);
        const float* wr = whh + (size_t)grow * HID + (chunk << 5);
#pragma unroll
        for (int q = 0; q < 8; ++q)
            wq[i][q] = __ldg((const float4*)(wr + q * 4));
    }
    if (tid < 64) {
        int grow = ((tid >> 4) << 8) + j0a + (tid & 15);
        sBias[tid] = bih[grow] + bhh[grow];
    }
    for (int i = tid; i < 4096; i += NTHREADS) hbuf[i] = 0.f;
    float creg = 0.f;
    __syncthreads();

    const int myLen = sLen[ub & 7];

    // zin sources + per-example time modes (0: t, 1: (t+len)%T, 2: (t+T-len)%T)
    const float *zsA, *zsB = nullptr;
    int mA, mB = 0;
    if (layer == 0)      { zsA = g_zin[dir]; mA = dir ? 1 : 0; }
    else if (dir == 0)   { zsA = g_zin[0]; mA = 0; zsB = g_zin[1]; mB = 2; }
    else                 { zsA = g_zin[2]; mA = 1; zsB = g_zin[3]; mB = 0; }

    auto tfix = [&](int mode, int s) -> int {
        int t = dir ? (TSEQ - 1 - s) : s;
        if (mode == 1) t += myLen;
        else if (mode == 2) t += TSEQ - myLen;
        if (t >= TSEQ) t -= TSEQ;
        return t;
    };

    // prime z prefetch (update threads only)
    float zA[4], zB[4];
    if (tid < 128) {
        size_t rA = (size_t)tfix(mA, 0) * BATCH + gb;
#pragma unroll
        for (int g = 0; g < 4; ++g) zA[g] = __ldg(zsA + rA * 1024 + (g << 8) + j0a + uu);
        if (zsB) {
            size_t rB = (size_t)tfix(mB, 0) * BATCH + gb;
#pragma unroll
            for (int g = 0; g < 4; ++g) zB[g] = __ldg(zsB + rB * 1024 + (g << 8) + j0a + uu);
        } else { zB[0] = zB[1] = zB[2] = zB[3] = 0.f; }
    }

    const uint32_t hbase = smem_u32(hbuf);
    float* hs0 = dir ? g_hs0b : g_hs0f;

    CLUSTER_BAR();   // all CTAs initialized before any DSMEM pushes

    for (int s = 0; s < TSEQ; ++s) {
        const int par = s & 1;
        const int t = dir ? (TSEQ - 1 - s) : s;

        float zcA[4], zcB[4];
        if (tid < 128) {
#pragma unroll
            for (int g = 0; g < 4; ++g) { zcA[g] = zA[g]; zcB[g] = zB[g]; }
            if (s + 1 < TSEQ) {   // prefetch next step's z (addresses independent of h)
                size_t rA = (size_t)tfix(mA, s + 1) * BATCH + gb;
#pragma unroll
                for (int g = 0; g < 4; ++g) zA[g] = __ldg(zsA + rA * 1024 + (g << 8) + j0a + uu);
                if (zsB) {
                    size_t rB = (size_t)tfix(mB, s + 1) * BATCH + gb;
#pragma unroll
                    for (int g = 0; g < 4; ++g) zB[g] = __ldg(zsB + rB * 1024 + (g << 8) + j0a + uu);
                }
            }
        }

        // ---- recurrent GEMM: reg W (2 rows), broadcast h, 8 batches ----
        ull acc[2][4];
#pragma unroll
        for (int i = 0; i < 2; ++i)
#pragma unroll
            for (int j = 0; j < 4; ++j) acc[i][j] = 0ull;
        {
            const float* hrow = hbuf + par * 2048 + (chunk << 8);   // [k-chunk of 32][8 b]
#pragma unroll
            for (int q = 0; q < 8; ++q) {
#pragma unroll
                for (int j = 0; j < 4; ++j) {
                    const float* hk = hrow + ((q << 2) + j) * 8;
                    ulonglong2 hp  = *(const ulonglong2*)hk;        // batches 0-3
                    ulonglong2 hp2 = *(const ulonglong2*)(hk + 4);  // batches 4-7
                    const float w0f = ((const float*)&wq[0][q])[j];
                    const float w1f = ((const float*)&wq[1][q])[j];
                    ull w0 = pck(w0f, w0f), w1 = pck(w1f, w1f);
                    fma2(acc[0][0], hp.x,  w0); fma2(acc[0][1], hp.y,  w0);
                    fma2(acc[0][2], hp2.x, w0); fma2(acc[0][3], hp2.y, w0);
                    fma2(acc[1][0], hp.x,  w1); fma2(acc[1][1], hp.y,  w1);
                    fma2(acc[1][2], hp2.x, w1); fma2(acc[1][3], hp2.y, w1);
                }
            }
        }
        {
            float* zr = zp + chunk * 640 + (rg * 2) * 10;   // even stride: 8B stores aligned
#pragma unroll
            for (int i = 0; i < 2; ++i)
#pragma unroll
                for (int bp = 0; bp < 4; ++bp)
                    *(ull*)(zr + i * 10 + bp * 2) = acc[i][bp];
        }
        __syncthreads();

        // ---- reduce + cell update: thread owns (unit uu, batch ub) ----
        if (tid < 128) {
            float zg4[4];
#pragma unroll
            for (int g = 0; g < 4; ++g) {
                int row = (g << 4) + uu;
                float v = zcA[g] + zcB[g] + sBias[row];
                const float* zpr = zp + row * 10 + ub;
#pragma unroll
                for (int c = 0; c < 8; ++c) v += zpr[c * 640];
                zg4[g] = v;
            }
            float ig = sigf(zg4[0]), fg = sigf(zg4[1]);
            float gg = tanhf(zg4[2]), og = sigf(zg4[3]);
            creg = fg * creg + ig * gg;
            float h = og * tanhf(creg);

            bool trig = dir ? (t == TSEQ - myLen) : (t == myLen - 1);
            if (trig) {   // final valid state for this example
                size_t o = OUT_LH + ((size_t)(layer * 2 + dir) * BATCH + gb) * HID + j0a + uu;
                p.out[o] = h;
                p.out[o + LHN] = creg;
            }
            if (layer == 0) {
                hs0[((size_t)t * BATCH + gb) * HID + j0a + uu] = h;
            } else {
                int tm = t, col = j0a + uu;
                if (dir) { tm = t + myLen; if (tm >= TSEQ) tm -= TSEQ; col += HID; }
                p.out[((size_t)tm * BATCH + gb) * (2 * HID) + col] = (tm < myLen) ? h : 0.f;
            }

            // stage own h locally: hbuf[par^1][j0a+uu][ub]
            hbuf[(par ^ 1) * 2048 + (j0a + uu) * 8 + ub] = h;
        }
        __syncthreads();

        // ---- vectorized DSMEM push: own 128-float block -> 15 peers ----
        {
            const uint32_t po = (uint32_t)((par ^ 1) * 8192 + j0a * 32);
#pragma unroll
            for (int it = 0; it < 2; ++it) {
                int item = tid + it * NTHREADS;           // 0..479 used
                if (item < 480) {
                    int rrk  = (ug + 1 + (item >> 5)) & 15;
                    uint32_t off = po + (uint32_t)((item & 31) << 4);
                    float4 v = *(const float4*)((const char*)hbuf + off);
                    uint32_t rad;
                    asm("mapa.shared::cluster.u32 %0, %1, %2;"
                        : "=r"(rad) : "r"(hbase + off), "r"(rrk));
                    asm volatile("st.shared::cluster.v4.b32 [%0], {%1, %2, %3, %4};"
                                 :: "r"(rad), "r"(__float_as_uint(v.x)), "r"(__float_as_uint(v.y)),
                                    "r"(__float_as_uint(v.z)), "r"(__float_as_uint(v.w)) : "memory");
                }
            }
        }

        CLUSTER_BAR();   // DSMEM h visible cluster-wide; also orders zp reuse
    }
}

extern "C" void kernel_launch(void* const* d_in, const int* in_sizes, int n_in,
                              void* d_out, int out_size) {
    Params P;
    P.x   = (const float*)d_in[0];
    P.len = (const int*)d_in[1];
    for (int i = 0; i < 16; ++i) P.w[i] = (const float*)d_in[2 + i];
    P.out = (float*)d_out;

    void *zp_, *hsf_, *hsb_;
    cudaGetSymbolAddress(&zp_,  g_zin);
    cudaGetSymbolAddress(&hsf_, g_hs0f);
    cudaGetSymbolAddress(&hsb_, g_hs0b);
    float* z = (float*)zp_;
    const float* hsf = (const float*)hsf_;
    const float* hsb = (const float*)hsb_;
    const size_t ZN = (size_t)MTOT * 1024;

    cudaFuncSetAttribute(scan_kernel, cudaFuncAttributeNonPortableClusterSizeAllowed, 1);
    cudaFuncSetAttribute(scan_kernel, cudaFuncAttributeMaxDynamicSharedMemorySize, SMEM_BYTES);

    dim3 gg(8, 1024);   // N-tiles x M-tiles

    // layer-0 input projections (K=256)
    gemm_k256<<<gg, 256>>>(P.x, P.w[0], 256, z);              // kernel 1 (fwd)
    gemm_k256<<<gg, 256>>>(P.x, P.w[4], 256, z + ZN);         // kernel 2 (bwd)

    noop_kernel<<<1, 32>>>();                                 // kernel 3 (ncu alignment)

    scan_kernel<<<256, NTHREADS, SMEM_BYTES>>>(P, 0);         // kernel 4 <- ncu target

    // layer-1 input projections: K=512 split into two K=256 halves
    gemm_k256<<<gg, 256>>>(hsf, P.w[8],        512, z);            // fwd, hsf-half
    gemm_k256<<<gg, 256>>>(hsb, P.w[8]  + 256, 512, z + ZN);       // fwd, hsb-half
    gemm_k256<<<gg, 256>>>(hsf, P.w[12],       512, z + 2 * ZN);   // bwd, hsf-half
    gemm_k256<<<gg, 256>>>(hsb, P.w[12] + 256, 512, z + 3 * ZN);   // bwd, hsb-half

    scan_kernel<<<256, NTHREADS, SMEM_BYTES>>>(P, 1);
}

// round 15
// speedup vs baseline: 2.3919x; 1.1376x over previous
#include <cuda_runtime.h>
#include <cuda_bf16.h>
#include <cstdint>

#define TSEQ 2048
#define BATCH 64
#define HID 256
#define NTHREADS 256
#define MTOT (TSEQ * BATCH)          // 131072 rows

#define OUT_LH 67108864UL            // T*B*2H
#define LHN    65536UL               // 4*B*H

typedef unsigned long long ull;
typedef unsigned short u16;

// ---- scratch (device statics are the sanctioned no-alloc path) ----
__device__ float g_zin[4][(size_t)MTOT * 1024];   // precomputed input projections
__device__ float g_hs0f[(size_t)MTOT * HID];
__device__ float g_hs0b[(size_t)MTOT * HID];
// bf16 hi/lo copies of GEMM A operands + W views
__device__ u16 g_xh[(size_t)MTOT * HID],  g_xl[(size_t)MTOT * HID];
__device__ u16 g_fh[(size_t)MTOT * HID],  g_fl[(size_t)MTOT * HID];
__device__ u16 g_bh[(size_t)MTOT * HID],  g_bl[(size_t)MTOT * HID];
__device__ u16 g_wh[6][1024 * 256], g_wl[6][1024 * 256];

struct Params {
    const float* __restrict__ x;
    const int*   __restrict__ len;
    const float* __restrict__ w[16];
    float*       __restrict__ out;
};

// ---------------- scan-phase shared memory layout (floats) ----------------
#define SM_ZP   4096
#define SM_BIAS 9216
#define SM_LEN  9280
#define SMEM_FLOATS 9288
#define SMEM_BYTES (SMEM_FLOATS * 4)

__device__ __forceinline__ ull pck(float lo, float hi) {
    ull r;
    asm("mov.b64 %0, {%1, %2};" : "=l"(r) : "f"(lo), "f"(hi));
    return r;
}
__device__ __forceinline__ void fma2(ull& d, ull a, ull b) {
    asm("fma.rn.f32x2 %0, %1, %2, %0;" : "+l"(d) : "l"(a), "l"(b));
}
__device__ __forceinline__ float sigf(float x) {
    return __fdividef(1.f, 1.f + __expf(-x));
}
__device__ __forceinline__ uint32_t smem_u32(const void* p) {
    uint32_t a;
    asm("{ .reg .u64 t; cvta.to.shared.u64 t, %1; cvt.u32.u64 %0, t; }" : "=r"(a) : "l"(p));
    return a;
}
#define CLUSTER_BAR() do { \
    asm volatile("barrier.cluster.arrive.aligned;" ::: "memory"); \
    asm volatile("barrier.cluster.wait.aligned;"   ::: "memory"); } while (0)

__device__ __forceinline__ u16 bfu(float x) {
    __nv_bfloat16 b = __float2bfloat16(x);
    return *reinterpret_cast<u16*>(&b);
}
__device__ __forceinline__ float bff(u16 u) {
    __nv_bfloat16 b = *reinterpret_cast<__nv_bfloat16*>(&u);
    return __bfloat162float(b);
}

// =======================================================================
// conv_split: fp32 array -> bf16 hi + bf16 lo (residual)
// =======================================================================
__global__ void __launch_bounds__(256)
conv_split(const float* __restrict__ src, u16* __restrict__ hi,
           u16* __restrict__ lo, int n4)
{
    int i = blockIdx.x * 256 + threadIdx.x;
    if (i >= n4) return;
    float4 v = __ldg((const float4*)src + i);
    ushort4 H, L;
    H.x = bfu(v.x); L.x = bfu(v.x - bff(H.x));
    H.y = bfu(v.y); L.y = bfu(v.y - bff(H.y));
    H.z = bfu(v.z); L.z = bfu(v.z - bff(H.z));
    H.w = bfu(v.w); L.w = bfu(v.w - bff(H.w));
    ((ushort4*)hi)[i] = H;
    ((ushort4*)lo)[i] = L;
}

// =======================================================================
// conv_w: 6 weight views [1024 rows x 256 k] -> bf16 hi/lo
// views: 0:(w0,256,0) 1:(w4,256,0) 2:(w8,512,0) 3:(w8,512,256)
//        4:(w12,512,0) 5:(w12,512,256)
// =======================================================================
__global__ void __launch_bounds__(256)
conv_w(Params p, u16* __restrict__ wh, u16* __restrict__ wl)
{
    int v = blockIdx.y, row = blockIdx.x, k = threadIdx.x;
    const float* src; int ldw, off;
    switch (v) {
        case 0: src = p.w[0];  ldw = 256; off = 0;   break;
        case 1: src = p.w[4];  ldw = 256; off = 0;   break;
        case 2: src = p.w[8];  ldw = 512; off = 0;   break;
        case 3: src = p.w[8];  ldw = 512; off = 256; break;
        case 4: src = p.w[12]; ldw = 512; off = 0;   break;
        default: src = p.w[12]; ldw = 512; off = 256; break;
    }
    float x = __ldg(src + (size_t)row * ldw + off + k);
    u16 h = bfu(x);
    size_t o = ((size_t)v * 1024 + row) * 256 + k;
    wh[o] = h;
    wl[o] = bfu(x - bff(h));
}

// =======================================================================
// Tensor-core GEMM: C[M,1024] = A[M,256] @ W[1024,256]^T via bf16 split
// C = Ah*Wh + Ah*Wl + Al*Wh  (fp32 accum). Block tile 128(M) x 64(N),
// 8 warps (4m x 2n), warp tile 32x32 = 2x4 m16n8k16 tiles, K-chunk 32.
// =======================================================================
#define MMA16816(c, a, b) \
    asm volatile("mma.sync.aligned.m16n8k16.row.col.f32.bf16.bf16.f32 " \
        "{%0,%1,%2,%3}, {%4,%5,%6,%7}, {%8,%9}, {%0,%1,%2,%3};" \
        : "+f"((c)[0]), "+f"((c)[1]), "+f"((c)[2]), "+f"((c)[3]) \
        : "r"((a)[0]), "r"((a)[1]), "r"((a)[2]), "r"((a)[3]), \
          "r"((b)[0]), "r"((b)[1]))

__global__ void __launch_bounds__(256, 2)
gemm_bf16(const u16* __restrict__ Ah, const u16* __restrict__ Al,
          const u16* __restrict__ Wh, const u16* __restrict__ Wl,
          float* __restrict__ C)
{
    __shared__ u16 sA[2][128][40];   // [ver][m][k], stride 40 (80B) bank-spread
    __shared__ u16 sW[2][64][40];    // [ver][n][k]

    const int tid  = threadIdx.x;
    const int wid  = tid >> 5, lane = tid & 31;
    const int wm   = wid >> 1, wn = wid & 1;
    const int grp  = lane >> 2, qp = lane & 3;
    const int m0   = blockIdx.y << 7;
    const int n0   = blockIdx.x << 6;

    float acc[2][4][4];
#pragma unroll
    for (int i = 0; i < 2; ++i)
#pragma unroll
        for (int j = 0; j < 4; ++j)
#pragma unroll
            for (int q = 0; q < 4; ++q) acc[i][j][q] = 0.f;

    const int ar = tid >> 2, aq = tid & 3;         // A loads: 128 rows x 4 quads (x2 iters)
    for (int kc = 0; kc < 256; kc += 32) {
        __syncthreads();
#pragma unroll
        for (int it = 0; it < 2; ++it) {
            int item = tid + (it << 8);
            int r = item >> 2, q = item & 3;
            *(uint4*)&sA[0][r][q * 8] = *(const uint4*)(Ah + (((size_t)(m0 + r)) << 8) + kc + q * 8);
            *(uint4*)&sA[1][r][q * 8] = *(const uint4*)(Al + (((size_t)(m0 + r)) << 8) + kc + q * 8);
        }
        {
            int r = ar & 63, q = aq;   // 64 rows x 4 quads (256 items exactly)
            *(uint4*)&sW[0][r][q * 8] = *(const uint4*)(Wh + (((size_t)(n0 + r)) << 8) + kc + q * 8);
            *(uint4*)&sW[1][r][q * 8] = *(const uint4*)(Wl + (((size_t)(n0 + r)) << 8) + kc + q * 8);
        }
        __syncthreads();

#pragma unroll
        for (int ks = 0; ks < 32; ks += 16) {
            unsigned a[2][2][4];   // [ver][mt][4]
#pragma unroll
            for (int ver = 0; ver < 2; ++ver)
#pragma unroll
                for (int mt = 0; mt < 2; ++mt) {
                    int mb = wm * 32 + mt * 16;
                    a[ver][mt][0] = *(const unsigned*)&sA[ver][mb + grp][ks + qp * 2];
                    a[ver][mt][1] = *(const unsigned*)&sA[ver][mb + grp + 8][ks + qp * 2];
                    a[ver][mt][2] = *(const unsigned*)&sA[ver][mb + grp][ks + qp * 2 + 8];
                    a[ver][mt][3] = *(const unsigned*)&sA[ver][mb + grp + 8][ks + qp * 2 + 8];
                }
            unsigned b[2][4][2];   // [ver][nt][2]
#pragma unroll
            for (int ver = 0; ver < 2; ++ver)
#pragma unroll
                for (int nt = 0; nt < 4; ++nt) {
                    int nb = wn * 32 + nt * 8;
                    b[ver][nt][0] = *(const unsigned*)&sW[ver][nb + grp][ks + qp * 2];
                    b[ver][nt][1] = *(const unsigned*)&sW[ver][nb + grp][ks + qp * 2 + 8];
                }
#pragma unroll
            for (int mt = 0; mt < 2; ++mt)
#pragma unroll
                for (int nt = 0; nt < 4; ++nt) {
                    MMA16816(acc[mt][nt], a[0][mt], b[0][nt]);   // hi*hi
                    MMA16816(acc[mt][nt], a[0][mt], b[1][nt]);   // hi*lo
                    MMA16816(acc[mt][nt], a[1][mt], b[0][nt]);   // lo*hi
                }
        }
    }

#pragma unroll
    for (int mt = 0; mt < 2; ++mt)
#pragma unroll
        for (int nt = 0; nt < 4; ++nt) {
            size_t row0 = (size_t)(m0 + wm * 32 + mt * 16 + grp);
            int col = n0 + wn * 32 + nt * 8 + qp * 2;
            *(float2*)(C + row0 * 1024 + col)       = make_float2(acc[mt][nt][0], acc[mt][nt][1]);
            *(float2*)(C + (row0 + 8) * 1024 + col) = make_float2(acc[mt][nt][2], acc[mt][nt][3]);
        }
}

// =======================================================================
// Persistent recurrent scan — 16-CTA cluster, occupancy 2 (UNCHANGED R14)
// =======================================================================
__global__ void __launch_bounds__(NTHREADS, 2) __cluster_dims__(16, 1, 1)
scan_kernel(Params p, int layer)
{
    extern __shared__ float sm[];
    float* hbuf  = sm;                    // [2][256][8]
    float* zp    = sm + SM_ZP;            // [8][64][10]
    float* sBias = sm + SM_BIAS;          // [64]
    int*   sLen  = (int*)(sm + SM_LEN);   // [8]

    const int tid = threadIdx.x;
    const int bid = blockIdx.x;
    const int dir = bid >> 7;
    const int bg  = (bid >> 4) & 7;
    const int ug  = bid & 15;             // == cluster rank
    const int j0a = ug << 4;              // absolute unit base (16 units)
    const int chunk = tid >> 5;           // k-chunk (warp)
    const int rg    = tid & 31;           // 2-row group (lane)
    const int ub = tid >> 4;              // local batch 0..7 (update role)
    const int uu = tid & 15;              // unit 0..15
    const int gb = (bg << 3) + ub;        // global batch

    if (tid < 8) sLen[tid] = p.len[(bg << 3) + tid];

    const float* whh = p.w[layer * 8 + dir * 4 + 1];
    const float* bih = p.w[layer * 8 + dir * 4 + 2];
    const float* bhh = p.w[layer * 8 + dir * 4 + 3];

    float4 wq[2][8];
#pragma unroll
    for (int i = 0; i < 2; ++i) {
        int lr = rg * 2 + i;
        int grow = ((lr >> 4) << 8) + j0a + (lr & 15);
        const float* wr = whh + (size_t)grow * HID + (chunk << 5);
#pragma unroll
        for (int q = 0; q < 8; ++q)
            wq[i][q] = __ldg((const float4*)(wr + q * 4));
    }
    if (tid < 64) {
        int grow = ((tid >> 4) << 8) + j0a + (tid & 15);
        sBias[tid] = bih[grow] + bhh[grow];
    }
    for (int i = tid; i < 4096; i += NTHREADS) hbuf[i] = 0.f;
    float creg = 0.f;
    __syncthreads();

    const int myLen = sLen[ub & 7];

    const float *zsA, *zsB = nullptr;
    int mA, mB = 0;
    if (layer == 0)      { zsA = g_zin[dir]; mA = dir ? 1 : 0; }
    else if (dir == 0)   { zsA = g_zin[0]; mA = 0; zsB = g_zin[1]; mB = 2; }
    else                 { zsA = g_zin[2]; mA = 1; zsB = g_zin[3]; mB = 0; }

    auto tfix = [&](int mode, int s) -> int {
        int t = dir ? (TSEQ - 1 - s) : s;
        if (mode == 1) t += myLen;
        else if (mode == 2) t += TSEQ - myLen;
        if (t >= TSEQ) t -= TSEQ;
        return t;
    };

    float zA[4], zB[4];
    if (tid < 128) {
        size_t rA = (size_t)tfix(mA, 0) * BATCH + gb;
#pragma unroll
        for (int g = 0; g < 4; ++g) zA[g] = __ldg(zsA + rA * 1024 + (g << 8) + j0a + uu);
        if (zsB) {
            size_t rB = (size_t)tfix(mB, 0) * BATCH + gb;
#pragma unroll
            for (int g = 0; g < 4; ++g) zB[g] = __ldg(zsB + rB * 1024 + (g << 8) + j0a + uu);
        } else { zB[0] = zB[1] = zB[2] = zB[3] = 0.f; }
    }

    const uint32_t hbase = smem_u32(hbuf);
    float* hs0 = dir ? g_hs0b : g_hs0f;

    CLUSTER_BAR();

    for (int s = 0; s < TSEQ; ++s) {
        const int par = s & 1;
        const int t = dir ? (TSEQ - 1 - s) : s;

        float zcA[4], zcB[4];
        if (tid < 128) {
#pragma unroll
            for (int g = 0; g < 4; ++g) { zcA[g] = zA[g]; zcB[g] = zB[g]; }
            if (s + 1 < TSEQ) {
                size_t rA = (size_t)tfix(mA, s + 1) * BATCH + gb;
#pragma unroll
                for (int g = 0; g < 4; ++g) zA[g] = __ldg(zsA + rA * 1024 + (g << 8) + j0a + uu);
                if (zsB) {
                    size_t rB = (size_t)tfix(mB, s + 1) * BATCH + gb;
#pragma unroll
                    for (int g = 0; g < 4; ++g) zB[g] = __ldg(zsB + rB * 1024 + (g << 8) + j0a + uu);
                }
            }
        }

        ull acc[2][4];
#pragma unroll
        for (int i = 0; i < 2; ++i)
#pragma unroll
            for (int j = 0; j < 4; ++j) acc[i][j] = 0ull;
        {
            const float* hrow = hbuf + par * 2048 + (chunk << 8);
#pragma unroll
            for (int q = 0; q < 8; ++q) {
#pragma unroll
                for (int j = 0; j < 4; ++j) {
                    const float* hk = hrow + ((q << 2) + j) * 8;
                    ulonglong2 hp  = *(const ulonglong2*)hk;
                    ulonglong2 hp2 = *(const ulonglong2*)(hk + 4);
                    const float w0f = ((const float*)&wq[0][q])[j];
                    const float w1f = ((const float*)&wq[1][q])[j];
                    ull w0 = pck(w0f, w0f), w1 = pck(w1f, w1f);
                    fma2(acc[0][0], hp.x,  w0); fma2(acc[0][1], hp.y,  w0);
                    fma2(acc[0][2], hp2.x, w0); fma2(acc[0][3], hp2.y, w0);
                    fma2(acc[1][0], hp.x,  w1); fma2(acc[1][1], hp.y,  w1);
                    fma2(acc[1][2], hp2.x, w1); fma2(acc[1][3], hp2.y, w1);
                }
            }
        }
        {
            float* zr = zp + chunk * 640 + (rg * 2) * 10;
#pragma unroll
            for (int i = 0; i < 2; ++i)
#pragma unroll
                for (int bp = 0; bp < 4; ++bp)
                    *(ull*)(zr + i * 10 + bp * 2) = acc[i][bp];
        }
        __syncthreads();

        if (tid < 128) {
            float zg4[4];
#pragma unroll
            for (int g = 0; g < 4; ++g) {
                int row = (g << 4) + uu;
                float v = zcA[g] + zcB[g] + sBias[row];
                const float* zpr = zp + row * 10 + ub;
#pragma unroll
                for (int c = 0; c < 8; ++c) v += zpr[c * 640];
                zg4[g] = v;
            }
            float ig = sigf(zg4[0]), fg = sigf(zg4[1]);
            float gg = tanhf(zg4[2]), og = sigf(zg4[3]);
            creg = fg * creg + ig * gg;
            float h = og * tanhf(creg);

            bool trig = dir ? (t == TSEQ - myLen) : (t == myLen - 1);
            if (trig) {
                size_t o = OUT_LH + ((size_t)(layer * 2 + dir) * BATCH + gb) * HID + j0a + uu;
                p.out[o] = h;
                p.out[o + LHN] = creg;
            }
            if (layer == 0) {
                hs0[((size_t)t * BATCH + gb) * HID + j0a + uu] = h;
            } else {
                int tm = t, col = j0a + uu;
                if (dir) { tm = t + myLen; if (tm >= TSEQ) tm -= TSEQ; col += HID; }
                p.out[((size_t)tm * BATCH + gb) * (2 * HID) + col] = (tm < myLen) ? h : 0.f;
            }

            hbuf[(par ^ 1) * 2048 + (j0a + uu) * 8 + ub] = h;
        }
        __syncthreads();

        {
            const uint32_t po = (uint32_t)((par ^ 1) * 8192 + j0a * 32);
#pragma unroll
            for (int it = 0; it < 2; ++it) {
                int item = tid + it * NTHREADS;
                if (item < 480) {
                    int rrk  = (ug + 1 + (item >> 5)) & 15;
                    uint32_t off = po + (uint32_t)((item & 31) << 4);
                    float4 v = *(const float4*)((const char*)hbuf + off);
                    uint32_t rad;
                    asm("mapa.shared::cluster.u32 %0, %1, %2;"
                        : "=r"(rad) : "r"(hbase + off), "r"(rrk));
                    asm volatile("st.shared::cluster.v4.b32 [%0], {%1, %2, %3, %4};"
                                 :: "r"(rad), "r"(__float_as_uint(v.x)), "r"(__float_as_uint(v.y)),
                                    "r"(__float_as_uint(v.z)), "r"(__float_as_uint(v.w)) : "memory");
                }
            }
        }

        CLUSTER_BAR();
    }
}

extern "C" void kernel_launch(void* const* d_in, const int* in_sizes, int n_in,
                              void* d_out, int out_size) {
    Params P;
    P.x   = (const float*)d_in[0];
    P.len = (const int*)d_in[1];
    for (int i = 0; i < 16; ++i) P.w[i] = (const float*)d_in[2 + i];
    P.out = (float*)d_out;

    void *zp_, *hsf_, *hsb_;
    void *xh_, *xl_, *fh_, *fl_, *bh_, *bl_, *wh_, *wl_;
    cudaGetSymbolAddress(&zp_,  g_zin);
    cudaGetSymbolAddress(&hsf_, g_hs0f);
    cudaGetSymbolAddress(&hsb_, g_hs0b);
    cudaGetSymbolAddress(&xh_, g_xh);  cudaGetSymbolAddress(&xl_, g_xl);
    cudaGetSymbolAddress(&fh_, g_fh);  cudaGetSymbolAddress(&fl_, g_fl);
    cudaGetSymbolAddress(&bh_, g_bh);  cudaGetSymbolAddress(&bl_, g_bl);
    cudaGetSymbolAddress(&wh_, g_wh);  cudaGetSymbolAddress(&wl_, g_wl);
    float* z = (float*)zp_;
    u16 *xh = (u16*)xh_, *xl = (u16*)xl_;
    u16 *fh = (u16*)fh_, *fl = (u16*)fl_;
    u16 *bh = (u16*)bh_, *bl = (u16*)bl_;
    u16 *wh = (u16*)wh_, *wl = (u16*)wl_;
    const size_t ZN = (size_t)MTOT * 1024;
    const size_t WV = 1024 * 256;
    const int N4 = MTOT * HID / 4;

    cudaFuncSetAttribute(scan_kernel, cudaFuncAttributeNonPortableClusterSizeAllowed, 1);
    cudaFuncSetAttribute(scan_kernel, cudaFuncAttributeMaxDynamicSharedMemorySize, SMEM_BYTES);

    dim3 gg(16, 1024);   // N-tiles(64) x M-tiles(128)

    conv_w<<<dim3(1024, 6), 256>>>(P, wh, wl);                        // k1
    conv_split<<<N4 / 256, 256>>>(P.x, xh, xl, N4);                   // k2

    // layer-0 input projections
    gemm_bf16<<<gg, 256>>>(xh, xl, wh + 0 * WV, wl + 0 * WV, z);      // k3 (fwd)
    gemm_bf16<<<gg, 256>>>(xh, xl, wh + 1 * WV, wl + 1 * WV, z + ZN); // k4 (bwd) <- ncu

    scan_kernel<<<256, NTHREADS, SMEM_BYTES>>>(P, 0);                 // k5

    conv_split<<<N4 / 256, 256>>>((const float*)hsf_, fh, fl, N4);    // k6
    conv_split<<<N4 / 256, 256>>>((const float*)hsb_, bh, bl, N4);    // k7

    // layer-1 input projections (K=512 split into two K=256 halves)
    gemm_bf16<<<gg, 256>>>(fh, fl, wh + 2 * WV, wl + 2 * WV, z);           // fwd, hsf
    gemm_bf16<<<gg, 256>>>(bh, bl, wh + 3 * WV, wl + 3 * WV, z + ZN);      // fwd, hsb
    gemm_bf16<<<gg, 256>>>(fh, fl, wh + 4 * WV, wl + 4 * WV, z + 2 * ZN);  // bwd, hsf
    gemm_bf16<<<gg, 256>>>(bh, bl, wh + 5 * WV, wl + 5 * WV, z + 3 * ZN);  // bwd, hsb

    scan_kernel<<<256, NTHREADS, SMEM_BYTES>>>(P, 1);
}

// round 16
// speedup vs baseline: 2.5196x; 1.0534x over previous
#include <cuda_runtime.h>
#include <cuda_bf16.h>
#include <cstdint>

#define TSEQ 2048
#define BATCH 64
#define HID 256
#define NTHREADS 256
#define MTOT (TSEQ * BATCH)          // 131072 rows

#define OUT_LH 67108864UL            // T*B*2H
#define LHN    65536UL               // 4*B*H

typedef unsigned long long ull;
typedef unsigned short u16;

// ---- scratch (device statics are the sanctioned no-alloc path) ----
__device__ float g_zin[4][(size_t)MTOT * 1024];   // precomputed input projections
__device__ float g_hs0f[(size_t)MTOT * HID];
__device__ float g_hs0b[(size_t)MTOT * HID];
// bf16 hi/lo copies of GEMM A operands + W views
__device__ u16 g_xh[(size_t)MTOT * HID],  g_xl[(size_t)MTOT * HID];
__device__ u16 g_fh[(size_t)MTOT * HID],  g_fl[(size_t)MTOT * HID];
__device__ u16 g_bh[(size_t)MTOT * HID],  g_bl[(size_t)MTOT * HID];
__device__ u16 g_wh[6][1024 * 256], g_wl[6][1024 * 256];

struct Params {
    const float* __restrict__ x;
    const int*   __restrict__ len;
    const float* __restrict__ w[16];
    float*       __restrict__ out;
};

// ---------------- scan-phase shared memory layout (floats) ----------------
#define SM_ZP   4096
#define SM_BIAS 9216
#define SM_LEN  9280
#define SMEM_FLOATS 9288
#define SMEM_BYTES (SMEM_FLOATS * 4)

__device__ __forceinline__ ull pck(float lo, float hi) {
    ull r;
    asm("mov.b64 %0, {%1, %2};" : "=l"(r) : "f"(lo), "f"(hi));
    return r;
}
__device__ __forceinline__ void fma2(ull& d, ull a, ull b) {
    asm("fma.rn.f32x2 %0, %1, %2, %0;" : "+l"(d) : "l"(a), "l"(b));
}
__device__ __forceinline__ float sigf(float x) {
    return __fdividef(1.f, 1.f + __expf(-x));
}
__device__ __forceinline__ uint32_t smem_u32(const void* p) {
    uint32_t a;
    asm("{ .reg .u64 t; cvta.to.shared.u64 t, %1; cvt.u32.u64 %0, t; }" : "=r"(a) : "l"(p));
    return a;
}
#define CLUSTER_BAR() do { \
    asm volatile("barrier.cluster.arrive.aligned;" ::: "memory"); \
    asm volatile("barrier.cluster.wait.aligned;"   ::: "memory"); } while (0)

__device__ __forceinline__ u16 bfu(float x) {
    __nv_bfloat16 b = __float2bfloat16(x);
    return *reinterpret_cast<u16*>(&b);
}
__device__ __forceinline__ float bff(u16 u) {
    __nv_bfloat16 b = *reinterpret_cast<__nv_bfloat16*>(&u);
    return __bfloat162float(b);
}

// =======================================================================
// conv_split: fp32 array -> bf16 hi + bf16 lo (residual)
// =======================================================================
__global__ void __launch_bounds__(256)
conv_split(const float* __restrict__ src, u16* __restrict__ hi,
           u16* __restrict__ lo, int n4)
{
    int i = blockIdx.x * 256 + threadIdx.x;
    if (i >= n4) return;
    float4 v = __ldg((const float4*)src + i);
    ushort4 H, L;
    H.x = bfu(v.x); L.x = bfu(v.x - bff(H.x));
    H.y = bfu(v.y); L.y = bfu(v.y - bff(H.y));
    H.z = bfu(v.z); L.z = bfu(v.z - bff(H.z));
    H.w = bfu(v.w); L.w = bfu(v.w - bff(H.w));
    ((ushort4*)hi)[i] = H;
    ((ushort4*)lo)[i] = L;
}

// =======================================================================
// conv_w: 6 weight views [1024 rows x 256 k] -> bf16 hi/lo
// =======================================================================
__global__ void __launch_bounds__(256)
conv_w(Params p, u16* __restrict__ wh, u16* __restrict__ wl)
{
    int v = blockIdx.y, row = blockIdx.x, k = threadIdx.x;
    const float* src; int ldw, off;
    switch (v) {
        case 0: src = p.w[0];  ldw = 256; off = 0;   break;
        case 1: src = p.w[4];  ldw = 256; off = 0;   break;
        case 2: src = p.w[8];  ldw = 512; off = 0;   break;
        case 3: src = p.w[8];  ldw = 512; off = 256; break;
        case 4: src = p.w[12]; ldw = 512; off = 0;   break;
        default: src = p.w[12]; ldw = 512; off = 256; break;
    }
    float x = __ldg(src + (size_t)row * ldw + off + k);
    u16 h = bfu(x);
    size_t o = ((size_t)v * 1024 + row) * 256 + k;
    wh[o] = h;
    wl[o] = bfu(x - bff(h));
}

// =======================================================================
// Tensor-core GEMM v2: C[M,1024] = A[M,256] @ W[1024,256]^T, bf16 split
// (Ah*Wh + Ah*Wl + Al*Wh, fp32 accum). Block 128m x 64n, 8 warps
// (warp 32x32 = 2x4 m16n8k16). cp.async 2-stage pipeline + ldmatrix.
// smem rows stride 40 u16 (80B): ldmatrix's 8 row-ptrs hit 8 distinct banks.
// =======================================================================
#define MMA16816(c, a, b) \
    asm volatile("mma.sync.aligned.m16n8k16.row.col.f32.bf16.bf16.f32 " \
        "{%0,%1,%2,%3}, {%4,%5,%6,%7}, {%8,%9}, {%0,%1,%2,%3};" \
        : "+f"((c)[0]), "+f"((c)[1]), "+f"((c)[2]), "+f"((c)[3]) \
        : "r"((a)[0]), "r"((a)[1]), "r"((a)[2]), "r"((a)[3]), \
          "r"((b)[0]), "r"((b)[1]))

#define LDSM_X4(r0, r1, r2, r3, addr) \
    asm volatile("ldmatrix.sync.aligned.m8n8.x4.shared.b16 {%0,%1,%2,%3}, [%4];" \
        : "=r"(r0), "=r"(r1), "=r"(r2), "=r"(r3) : "r"(addr))

#define CPA16(sa, gp) \
    asm volatile("cp.async.cg.shared.global [%0], [%1], 16;" :: "r"(sa), "l"(gp))

// u16 offsets into dynamic smem
#define GA(st, ver, m, k) ((((st) * 2 + (ver)) * 128 + (m)) * 40 + (k))
#define GW(st, ver, n, k) (20480 + (((st) * 2 + (ver)) * 64 + (n)) * 40 + (k))
#define GEMM_SMEM_BYTES ((20480 + 10240) * 2)   // 61440

__global__ void __launch_bounds__(256)
gemm_bf16(const u16* __restrict__ Ah, const u16* __restrict__ Al,
          const u16* __restrict__ Wh, const u16* __restrict__ Wl,
          float* __restrict__ C)
{
    extern __shared__ u16 smu[];
    const uint32_t sbase = smem_u32(smu);

    const int tid  = threadIdx.x;
    const int wid  = tid >> 5, lane = tid & 31;
    const int wm   = wid >> 1, wn = wid & 1;
    const int grp  = lane >> 2, qp = lane & 3;
    const int m0   = blockIdx.y << 7;
    const int n0   = blockIdx.x << 6;

    // ldmatrix lane-address components
    const int aRow = ((lane >> 3) & 1) * 8 + (lane & 7);   // + mb
    const int aK   = (lane >> 4) << 3;                      // + ks
    const int bRow = ((lane >> 4) << 3) + (lane & 7);       // + nb
    const int bK   = ((lane >> 3) & 1) << 3;                // + ks

    float acc[2][4][4];
#pragma unroll
    for (int i = 0; i < 2; ++i)
#pragma unroll
        for (int j = 0; j < 4; ++j)
#pragma unroll
            for (int q = 0; q < 4; ++q) acc[i][j][q] = 0.f;

    // ---- async copy of one 32-wide K chunk into stage st ----
    auto prefetch = [&](int st, int kc) {
#pragma unroll
        for (int i = 0; i < 4; ++i) {              // A: 2ver x 128r x 4q = 1024
            int item = tid + (i << 8);
            int ver = item >> 9, rem = item & 511;
            int r = rem >> 2, q = rem & 3;
            const u16* gp = (ver ? Al : Ah) + (((size_t)(m0 + r)) << 8) + kc + q * 8;
            CPA16(sbase + GA(st, ver, r, q * 8) * 2, gp);
        }
#pragma unroll
        for (int i = 0; i < 2; ++i) {              // W: 2ver x 64r x 4q = 512
            int item = tid + (i << 8);
            int ver = item >> 8, rem = item & 255;
            int r = rem >> 2, q = rem & 3;
            const u16* gp = (ver ? Wl : Wh) + (((size_t)(n0 + r)) << 8) + kc + q * 8;
            CPA16(sbase + GW(st, ver, r, q * 8) * 2, gp);
        }
        asm volatile("cp.async.commit_group;");
    };

    prefetch(0, 0);

    for (int i = 0; i < 8; ++i) {
        const int st = i & 1;
        if (i < 7) {
            prefetch(st ^ 1, (i + 1) << 5);
            asm volatile("cp.async.wait_group 1;");
        } else {
            asm volatile("cp.async.wait_group 0;");
        }
        __syncthreads();

#pragma unroll
        for (int ks = 0; ks < 32; ks += 16) {
            unsigned a[2][2][4];
#pragma unroll
            for (int ver = 0; ver < 2; ++ver)
#pragma unroll
                for (int mt = 0; mt < 2; ++mt) {
                    int mb = wm * 32 + mt * 16;
                    uint32_t ad = sbase + GA(st, ver, mb + aRow, ks + aK) * 2;
                    LDSM_X4(a[ver][mt][0], a[ver][mt][1], a[ver][mt][2], a[ver][mt][3], ad);
                }
            unsigned b[2][4][2];
#pragma unroll
            for (int ver = 0; ver < 2; ++ver)
#pragma unroll
                for (int nt2 = 0; nt2 < 2; ++nt2) {
                    int nb = wn * 32 + nt2 * 16;
                    uint32_t ad = sbase + GW(st, ver, nb + bRow, ks + bK) * 2;
                    LDSM_X4(b[ver][nt2 * 2][0], b[ver][nt2 * 2][1],
                            b[ver][nt2 * 2 + 1][0], b[ver][nt2 * 2 + 1][1], ad);
                }
#pragma unroll
            for (int mt = 0; mt < 2; ++mt)
#pragma unroll
                for (int nt = 0; nt < 4; ++nt) {
                    MMA16816(acc[mt][nt], a[0][mt], b[0][nt]);   // hi*hi
                    MMA16816(acc[mt][nt], a[0][mt], b[1][nt]);   // hi*lo
                    MMA16816(acc[mt][nt], a[1][mt], b[0][nt]);   // lo*hi
                }
        }
        __syncthreads();
    }

#pragma unroll
    for (int mt = 0; mt < 2; ++mt)
#pragma unroll
        for (int nt = 0; nt < 4; ++nt) {
            size_t row0 = (size_t)(m0 + wm * 32 + mt * 16 + grp);
            int col = n0 + wn * 32 + nt * 8 + qp * 2;
            *(float2*)(C + row0 * 1024 + col)       = make_float2(acc[mt][nt][0], acc[mt][nt][1]);
            *(float2*)(C + (row0 + 8) * 1024 + col) = make_float2(acc[mt][nt][2], acc[mt][nt][3]);
        }
}

// =======================================================================
// Persistent recurrent scan — 16-CTA cluster, occupancy 2 (UNCHANGED R14)
// =======================================================================
__global__ void __launch_bounds__(NTHREADS, 2) __cluster_dims__(16, 1, 1)
scan_kernel(Params p, int layer)
{
    extern __shared__ float sm[];
    float* hbuf  = sm;                    // [2][256][8]
    float* zp    = sm + SM_ZP;            // [8][64][10]
    float* sBias = sm + SM_BIAS;          // [64]
    int*   sLen  = (int*)(sm + SM_LEN);   // [8]

    const int tid = threadIdx.x;
    const int bid = blockIdx.x;
    const int dir = bid >> 7;
    const int bg  = (bid >> 4) & 7;
    const int ug  = bid & 15;             // == cluster rank
    const int j0a = ug << 4;              // absolute unit base (16 units)
    const int chunk = tid >> 5;           // k-chunk (warp)
    const int rg    = tid & 31;           // 2-row group (lane)
    const int ub = tid >> 4;              // local batch 0..7 (update role)
    const int uu = tid & 15;              // unit 0..15
    const int gb = (bg << 3) + ub;        // global batch

    if (tid < 8) sLen[tid] = p.len[(bg << 3) + tid];

    const float* whh = p.w[layer * 8 + dir * 4 + 1];
    const float* bih = p.w[layer * 8 + dir * 4 + 2];
    const float* bhh = p.w[layer * 8 + dir * 4 + 3];

    float4 wq[2][8];
#pragma unroll
    for (int i = 0; i < 2; ++i) {
        int lr = rg * 2 + i;
        int grow = ((lr >> 4) << 8) + j0a + (lr & 15);
        const float* wr = whh + (size_t)grow * HID + (chunk << 5);
#pragma unroll
        for (int q = 0; q < 8; ++q)
            wq[i][q] = __ldg((const float4*)(wr + q * 4));
    }
    if (tid < 64) {
        int grow = ((tid >> 4) << 8) + j0a + (tid & 15);
        sBias[tid] = bih[grow] + bhh[grow];
    }
    for (int i = tid; i < 4096; i += NTHREADS) hbuf[i] = 0.f;
    float creg = 0.f;
    __syncthreads();

    const int myLen = sLen[ub & 7];

    const float *zsA, *zsB = nullptr;
    int mA, mB = 0;
    if (layer == 0)      { zsA = g_zin[dir]; mA = dir ? 1 : 0; }
    else if (dir == 0)   { zsA = g_zin[0]; mA = 0; zsB = g_zin[1]; mB = 2; }
    else                 { zsA = g_zin[2]; mA = 1; zsB = g_zin[3]; mB = 0; }

    auto tfix = [&](int mode, int s) -> int {
        int t = dir ? (TSEQ - 1 - s) : s;
        if (mode == 1) t += myLen;
        else if (mode == 2) t += TSEQ - myLen;
        if (t >= TSEQ) t -= TSEQ;
        return t;
    };

    float zA[4], zB[4];
    if (tid < 128) {
        size_t rA = (size_t)tfix(mA, 0) * BATCH + gb;
#pragma unroll
        for (int g = 0; g < 4; ++g) zA[g] = __ldg(zsA + rA * 1024 + (g << 8) + j0a + uu);
        if (zsB) {
            size_t rB = (size_t)tfix(mB, 0) * BATCH + gb;
#pragma unroll
            for (int g = 0; g < 4; ++g) zB[g] = __ldg(zsB + rB * 1024 + (g << 8) + j0a + uu);
        } else { zB[0] = zB[1] = zB[2] = zB[3] = 0.f; }
    }

    const uint32_t hbase = smem_u32(hbuf);
    float* hs0 = dir ? g_hs0b : g_hs0f;

    CLUSTER_BAR();

    for (int s = 0; s < TSEQ; ++s) {
        const int par = s & 1;
        const int t = dir ? (TSEQ - 1 - s) : s;

        float zcA[4], zcB[4];
        if (tid < 128) {
#pragma unroll
            for (int g = 0; g < 4; ++g) { zcA[g] = zA[g]; zcB[g] = zB[g]; }
            if (s + 1 < TSEQ) {
                size_t rA = (size_t)tfix(mA, s + 1) * BATCH + gb;
#pragma unroll
                for (int g = 0; g < 4; ++g) zA[g] = __ldg(zsA + rA * 1024 + (g << 8) + j0a + uu);
                if (zsB) {
                    size_t rB = (size_t)tfix(mB, s + 1) * BATCH + gb;
#pragma unroll
                    for (int g = 0; g < 4; ++g) zB[g] = __ldg(zsB + rB * 1024 + (g << 8) + j0a + uu);
                }
            }
        }

        ull acc[2][4];
#pragma unroll
        for (int i = 0; i < 2; ++i)
#pragma unroll
            for (int j = 0; j < 4; ++j) acc[i][j] = 0ull;
        {
            const float* hrow = hbuf + par * 2048 + (chunk << 8);
#pragma unroll
            for (int q = 0; q < 8; ++q) {
#pragma unroll
                for (int j = 0; j < 4; ++j) {
                    const float* hk = hrow + ((q << 2) + j) * 8;
                    ulonglong2 hp  = *(const ulonglong2*)hk;
                    ulonglong2 hp2 = *(const ulonglong2*)(hk + 4);
                    const float w0f = ((const float*)&wq[0][q])[j];
                    const float w1f = ((const float*)&wq[1][q])[j];
                    ull w0 = pck(w0f, w0f), w1 = pck(w1f, w1f);
                    fma2(acc[0][0], hp.x,  w0); fma2(acc[0][1], hp.y,  w0);
                    fma2(acc[0][2], hp2.x, w0); fma2(acc[0][3], hp2.y, w0);
                    fma2(acc[1][0], hp.x,  w1); fma2(acc[1][1], hp.y,  w1);
                    fma2(acc[1][2], hp2.x, w1); fma2(acc[1][3], hp2.y, w1);
                }
            }
        }
        {
            float* zr = zp + chunk * 640 + (rg * 2) * 10;
#pragma unroll
            for (int i = 0; i < 2; ++i)
#pragma unroll
                for (int bp = 0; bp < 4; ++bp)
                    *(ull*)(zr + i * 10 + bp * 2) = acc[i][bp];
        }
        __syncthreads();

        if (tid < 128) {
            float zg4[4];
#pragma unroll
            for (int g = 0; g < 4; ++g) {
                int row = (g << 4) + uu;
                float v = zcA[g] + zcB[g] + sBias[row];
                const float* zpr = zp + row * 10 + ub;
#pragma unroll
                for (int c = 0; c < 8; ++c) v += zpr[c * 640];
                zg4[g] = v;
            }
            float ig = sigf(zg4[0]), fg = sigf(zg4[1]);
            float gg = tanhf(zg4[2]), og = sigf(zg4[3]);
            creg = fg * creg + ig * gg;
            float h = og * tanhf(creg);

            bool trig = dir ? (t == TSEQ - myLen) : (t == myLen - 1);
            if (trig) {
                size_t o = OUT_LH + ((size_t)(layer * 2 + dir) * BATCH + gb) * HID + j0a + uu;
                p.out[o] = h;
                p.out[o + LHN] = creg;
            }
            if (layer == 0) {
                hs0[((size_t)t * BATCH + gb) * HID + j0a + uu] = h;
            } else {
                int tm = t, col = j0a + uu;
                if (dir) { tm = t + myLen; if (tm >= TSEQ) tm -= TSEQ; col += HID; }
                p.out[((size_t)tm * BATCH + gb) * (2 * HID) + col] = (tm < myLen) ? h : 0.f;
            }

            hbuf[(par ^ 1) * 2048 + (j0a + uu) * 8 + ub] = h;
        }
        __syncthreads();

        {
            const uint32_t po = (uint32_t)((par ^ 1) * 8192 + j0a * 32);
#pragma unroll
            for (int it = 0; it < 2; ++it) {
                int item = tid + it * NTHREADS;
                if (item < 480) {
                    int rrk  = (ug + 1 + (item >> 5)) & 15;
                    uint32_t off = po + (uint32_t)((item & 31) << 4);
                    float4 v = *(const float4*)((const char*)hbuf + off);
                    uint32_t rad;
                    asm("mapa.shared::cluster.u32 %0, %1, %2;"
                        : "=r"(rad) : "r"(hbase + off), "r"(rrk));
                    asm volatile("st.shared::cluster.v4.b32 [%0], {%1, %2, %3, %4};"
                                 :: "r"(rad), "r"(__float_as_uint(v.x)), "r"(__float_as_uint(v.y)),
                                    "r"(__float_as_uint(v.z)), "r"(__float_as_uint(v.w)) : "memory");
                }
            }
        }

        CLUSTER_BAR();
    }
}

extern "C" void kernel_launch(void* const* d_in, const int* in_sizes, int n_in,
                              void* d_out, int out_size) {
    Params P;
    P.x   = (const float*)d_in[0];
    P.len = (const int*)d_in[1];
    for (int i = 0; i < 16; ++i) P.w[i] = (const float*)d_in[2 + i];
    P.out = (float*)d_out;

    void *zp_, *hsf_, *hsb_;
    void *xh_, *xl_, *fh_, *fl_, *bh_, *bl_, *wh_, *wl_;
    cudaGetSymbolAddress(&zp_,  g_zin);
    cudaGetSymbolAddress(&hsf_, g_hs0f);
    cudaGetSymbolAddress(&hsb_, g_hs0b);
    cudaGetSymbolAddress(&xh_, g_xh);  cudaGetSymbolAddress(&xl_, g_xl);
    cudaGetSymbolAddress(&fh_, g_fh);  cudaGetSymbolAddress(&fl_, g_fl);
    cudaGetSymbolAddress(&bh_, g_bh);  cudaGetSymbolAddress(&bl_, g_bl);
    cudaGetSymbolAddress(&wh_, g_wh);  cudaGetSymbolAddress(&wl_, g_wl);
    float* z = (float*)zp_;
    u16 *xh = (u16*)xh_, *xl = (u16*)xl_;
    u16 *fh = (u16*)fh_, *fl = (u16*)fl_;
    u16 *bh = (u16*)bh_, *bl = (u16*)bl_;
    u16 *wh = (u16*)wh_, *wl = (u16*)wl_;
    const size_t ZN = (size_t)MTOT * 1024;
    const size_t WV = 1024 * 256;
    const int N4 = MTOT * HID / 4;

    cudaFuncSetAttribute(scan_kernel, cudaFuncAttributeNonPortableClusterSizeAllowed, 1);
    cudaFuncSetAttribute(scan_kernel, cudaFuncAttributeMaxDynamicSharedMemorySize, SMEM_BYTES);
    cudaFuncSetAttribute(gemm_bf16, cudaFuncAttributeMaxDynamicSharedMemorySize, GEMM_SMEM_BYTES);

    dim3 gg(16, 1024);   // N-tiles(64) x M-tiles(128)

    conv_w<<<dim3(1024, 6), 256>>>(P, wh, wl);                        // k1
    conv_split<<<N4 / 256, 256>>>(P.x, xh, xl, N4);                   // k2

    // layer-0 input projections
    gemm_bf16<<<gg, 256, GEMM_SMEM_BYTES>>>(xh, xl, wh + 0 * WV, wl + 0 * WV, z);      // k3
    gemm_bf16<<<gg, 256, GEMM_SMEM_BYTES>>>(xh, xl, wh + 1 * WV, wl + 1 * WV, z + ZN); // k4 <- ncu

    scan_kernel<<<256, NTHREADS, SMEM_BYTES>>>(P, 0);                 // k5

    conv_split<<<N4 / 256, 256>>>((const float*)hsf_, fh, fl, N4);    // k6
    conv_split<<<N4 / 256, 256>>>((const float*)hsb_, bh, bl, N4);    // k7

    // layer-1 input projections (K=512 split into two K=256 halves)
    gemm_bf16<<<gg, 256, GEMM_SMEM_BYTES>>>(fh, fl, wh + 2 * WV, wl + 2 * WV, z);           // fwd, hsf
    gemm_bf16<<<gg, 256, GEMM_SMEM_BYTES>>>(bh, bl, wh + 3 * WV, wl + 3 * WV, z + ZN);      // fwd, hsb
    gemm_bf16<<<gg, 256, GEMM_SMEM_BYTES>>>(fh, fl, wh + 4 * WV, wl + 4 * WV, z + 2 * ZN);  // bwd, hsf
    gemm_bf16<<<gg, 256, GEMM_SMEM_BYTES>>>(bh, bl, wh + 5 * WV, wl + 5 * WV, z + 3 * ZN);  // bwd, hsb

    scan_kernel<<<256, NTHREADS, SMEM_BYTES>>>(P, 1);
}

// round 17
// speedup vs baseline: 3.0049x; 1.1926x over previous
#include <cuda_runtime.h>
#include <cuda_bf16.h>
#include <cstdint>

#define TSEQ 2048
#define BATCH 64
#define HID 256
#define NTHREADS 256
#define MTOT (TSEQ * BATCH)          // 131072 rows

#define OUT_LH 67108864UL            // T*B*2H
#define LHN    65536UL               // 4*B*H

typedef unsigned long long ull;
typedef unsigned short u16;

// ---- scratch (device statics are the sanctioned no-alloc path) ----
__device__ float g_zin[4][(size_t)MTOT * 1024];   // precomputed input projections
// bf16 hi/lo copies of GEMM A operands + W views
__device__ u16 g_xh[(size_t)MTOT * HID],  g_xl[(size_t)MTOT * HID];
__device__ u16 g_fh[(size_t)MTOT * HID],  g_fl[(size_t)MTOT * HID];   // layer0 fwd h (written by scan0)
__device__ u16 g_bh[(size_t)MTOT * HID],  g_bl[(size_t)MTOT * HID];   // layer0 bwd h
__device__ u16 g_wh[6][1024 * 256], g_wl[6][1024 * 256];

struct Params {
    const float* __restrict__ x;
    const int*   __restrict__ len;
    const float* __restrict__ w[16];
    float*       __restrict__ out;
};

__device__ __forceinline__ float sigf(float x) {
    return __fdividef(1.f, 1.f + __expf(-x));
}
__device__ __forceinline__ uint32_t smem_u32(const void* p) {
    uint32_t a;
    asm("{ .reg .u64 t; cvta.to.shared.u64 t, %1; cvt.u32.u64 %0, t; }" : "=r"(a) : "l"(p));
    return a;
}
#define CLUSTER_BAR() do { \
    asm volatile("barrier.cluster.arrive.aligned;" ::: "memory"); \
    asm volatile("barrier.cluster.wait.aligned;"   ::: "memory"); } while (0)

__device__ __forceinline__ u16 bfu(float x) {
    __nv_bfloat16 b = __float2bfloat16(x);
    return *reinterpret_cast<u16*>(&b);
}
__device__ __forceinline__ float bff(u16 u) {
    __nv_bfloat16 b = *reinterpret_cast<__nv_bfloat16*>(&u);
    return __bfloat162float(b);
}

#define MMA16816(c, a, b) \
    asm volatile("mma.sync.aligned.m16n8k16.row.col.f32.bf16.bf16.f32 " \
        "{%0,%1,%2,%3}, {%4,%5,%6,%7}, {%8,%9}, {%0,%1,%2,%3};" \
        : "+f"((c)[0]), "+f"((c)[1]), "+f"((c)[2]), "+f"((c)[3]) \
        : "r"((a)[0]), "r"((a)[1]), "r"((a)[2]), "r"((a)[3]), \
          "r"((b)[0]), "r"((b)[1]))

#define LDSM_X4(r0, r1, r2, r3, addr) \
    asm volatile("ldmatrix.sync.aligned.m8n8.x4.shared.b16 {%0,%1,%2,%3}, [%4];" \
        : "=r"(r0), "=r"(r1), "=r"(r2), "=r"(r3) : "r"(addr))

#define CPA16(sa, gp) \
    asm volatile("cp.async.cg.shared.global [%0], [%1], 16;" :: "r"(sa), "l"(gp))

// =======================================================================
// prep: fused conv_w (y==1) + conv_split of x (y==0)
// =======================================================================
__global__ void __launch_bounds__(256)
prep_kernel(Params p, u16* __restrict__ wh, u16* __restrict__ wl,
            u16* __restrict__ xh, u16* __restrict__ xl)
{
    if (blockIdx.y == 0) {
        int i = blockIdx.x * 256 + threadIdx.x;          // float4 index
        float4 v = __ldg((const float4*)p.x + i);
        ushort4 H, L;
        H.x = bfu(v.x); L.x = bfu(v.x - bff(H.x));
        H.y = bfu(v.y); L.y = bfu(v.y - bff(H.y));
        H.z = bfu(v.z); L.z = bfu(v.z - bff(H.z));
        H.w = bfu(v.w); L.w = bfu(v.w - bff(H.w));
        ((ushort4*)xh)[i] = H;
        ((ushort4*)xl)[i] = L;
    } else {
        if (blockIdx.x >= 6144) return;
        int v = blockIdx.x >> 10, row = blockIdx.x & 1023, k = threadIdx.x;
        const float* src; int ldw, off;
        switch (v) {
            case 0: src = p.w[0];  ldw = 256; off = 0;   break;
            case 1: src = p.w[4];  ldw = 256; off = 0;   break;
            case 2: src = p.w[8];  ldw = 512; off = 0;   break;
            case 3: src = p.w[8];  ldw = 512; off = 256; break;
            case 4: src = p.w[12]; ldw = 512; off = 0;   break;
            default: src = p.w[12]; ldw = 512; off = 256; break;
        }
        float x = __ldg(src + (size_t)row * ldw + off + k);
        u16 h = bfu(x);
        size_t o = ((size_t)v * 1024 + row) * 256 + k;
        wh[o] = h;
        wl[o] = bfu(x - bff(h));
    }
}

// =======================================================================
// Tensor-core GEMM (unchanged R16): C[M,1024] = A[M,256] @ W[1024,256]^T
// =======================================================================
#define GA(st, ver, m, k) ((((st) * 2 + (ver)) * 128 + (m)) * 40 + (k))
#define GW(st, ver, n, k) (20480 + (((st) * 2 + (ver)) * 64 + (n)) * 40 + (k))
#define GEMM_SMEM_BYTES ((20480 + 10240) * 2)   // 61440

__global__ void __launch_bounds__(256)
gemm_bf16(const u16* __restrict__ Ah, const u16* __restrict__ Al,
          const u16* __restrict__ Wh, const u16* __restrict__ Wl,
          float* __restrict__ C)
{
    extern __shared__ u16 smu[];
    const uint32_t sbase = smem_u32(smu);

    const int tid  = threadIdx.x;
    const int wid  = tid >> 5, lane = tid & 31;
    const int wm   = wid >> 1, wn = wid & 1;
    const int grp  = lane >> 2, qp = lane & 3;
    const int m0   = blockIdx.y << 7;
    const int n0   = blockIdx.x << 6;

    const int aRow = ((lane >> 3) & 1) * 8 + (lane & 7);
    const int aK   = (lane >> 4) << 3;
    const int bRow = ((lane >> 4) << 3) + (lane & 7);
    const int bK   = ((lane >> 3) & 1) << 3;

    float acc[2][4][4];
#pragma unroll
    for (int i = 0; i < 2; ++i)
#pragma unroll
        for (int j = 0; j < 4; ++j)
#pragma unroll
            for (int q = 0; q < 4; ++q) acc[i][j][q] = 0.f;

    auto prefetch = [&](int st, int kc) {
#pragma unroll
        for (int i = 0; i < 4; ++i) {
            int item = tid + (i << 8);
            int ver = item >> 9, rem = item & 511;
            int r = rem >> 2, q = rem & 3;
            const u16* gp = (ver ? Al : Ah) + (((size_t)(m0 + r)) << 8) + kc + q * 8;
            CPA16(sbase + GA(st, ver, r, q * 8) * 2, gp);
        }
#pragma unroll
        for (int i = 0; i < 2; ++i) {
            int item = tid + (i << 8);
            int ver = item >> 8, rem = item & 255;
            int r = rem >> 2, q = rem & 3;
            const u16* gp = (ver ? Wl : Wh) + (((size_t)(n0 + r)) << 8) + kc + q * 8;
            CPA16(sbase + GW(st, ver, r, q * 8) * 2, gp);
        }
        asm volatile("cp.async.commit_group;");
    };

    prefetch(0, 0);

    for (int i = 0; i < 8; ++i) {
        const int st = i & 1;
        if (i < 7) {
            prefetch(st ^ 1, (i + 1) << 5);
            asm volatile("cp.async.wait_group 1;");
        } else {
            asm volatile("cp.async.wait_group 0;");
        }
        __syncthreads();

#pragma unroll
        for (int ks = 0; ks < 32; ks += 16) {
            unsigned a[2][2][4];
#pragma unroll
            for (int ver = 0; ver < 2; ++ver)
#pragma unroll
                for (int mt = 0; mt < 2; ++mt) {
                    int mb = wm * 32 + mt * 16;
                    uint32_t ad = sbase + GA(st, ver, mb + aRow, ks + aK) * 2;
                    LDSM_X4(a[ver][mt][0], a[ver][mt][1], a[ver][mt][2], a[ver][mt][3], ad);
                }
            unsigned b[2][4][2];
#pragma unroll
            for (int ver = 0; ver < 2; ++ver)
#pragma unroll
                for (int nt2 = 0; nt2 < 2; ++nt2) {
                    int nb = wn * 32 + nt2 * 16;
                    uint32_t ad = sbase + GW(st, ver, nb + bRow, ks + bK) * 2;
                    LDSM_X4(b[ver][nt2 * 2][0], b[ver][nt2 * 2][1],
                            b[ver][nt2 * 2 + 1][0], b[ver][nt2 * 2 + 1][1], ad);
                }
#pragma unroll
            for (int mt = 0; mt < 2; ++mt)
#pragma unroll
                for (int nt = 0; nt < 4; ++nt) {
                    MMA16816(acc[mt][nt], a[0][mt], b[0][nt]);
                    MMA16816(acc[mt][nt], a[0][mt], b[1][nt]);
                    MMA16816(acc[mt][nt], a[1][mt], b[0][nt]);
                }
        }
        __syncthreads();
    }

#pragma unroll
    for (int mt = 0; mt < 2; ++mt)
#pragma unroll
        for (int nt = 0; nt < 4; ++nt) {
            size_t row0 = (size_t)(m0 + wm * 32 + mt * 16 + grp);
            int col = n0 + wn * 32 + nt * 8 + qp * 2;
            *(float2*)(C + row0 * 1024 + col)       = make_float2(acc[mt][nt][0], acc[mt][nt][1]);
            *(float2*)(C + (row0 + 8) * 1024 + col) = make_float2(acc[mt][nt][2], acc[mt][nt][3]);
        }
}

// =======================================================================
// Persistent recurrent scan — tensor-core recurrence.
// 16-CTA cluster, occupancy 2. CTA = 16 units (64 gate rows) x 8 batches.
// W_hh bf16 hi/lo lives in mma A-fragments (regs). h stored bf16 hi+lo
// in smem [b][264] (padded) — B-frag loads are plain conflict-free LDS.32.
// z = Wh*hH + Wh*hL + Wl*hH via m16n8k16 (mtile == gate). Partials
// reduced over the 8 k-chunk warps via zp smem, as before.
// =======================================================================
// smem (bytes): hH [2][8][264]u16 : 0     .. 8448
//               hL [2][8][264]u16 : 8448  .. 16896
//               zp [8][64][10]f32 : 16896 .. 37376
//               sBias[64]f32      : 37376 .. 37632
//               sLen[8]i32        : 37632 .. 37664
#define SCAN_HL   8448
#define SCAN_ZP   16896
#define SCAN_BIAS 37376
#define SCAN_LEN  37632
#define SCAN_SMEM 37664

__global__ void __launch_bounds__(NTHREADS, 2) __cluster_dims__(16, 1, 1)
scan_kernel(Params p, int layer)
{
    extern __shared__ char smc[];
    u16*   hH    = (u16*)smc;                     // [2][8][264]
    u16*   hL    = (u16*)(smc + SCAN_HL);
    float* zp    = (float*)(smc + SCAN_ZP);       // [8][64][10]
    float* sBias = (float*)(smc + SCAN_BIAS);     // [64]
    int*   sLen  = (int*)(smc + SCAN_LEN);        // [8]

    const int tid = threadIdx.x;
    const int bid = blockIdx.x;
    const int dir = bid >> 7;
    const int bg  = (bid >> 4) & 7;
    const int ug  = bid & 15;             // cluster rank
    const int j0a = ug << 4;              // unit base (16 units)
    const int chunk = tid >> 5;           // k-chunk warp (32 k)
    const int lane  = tid & 31;
    const int grp   = lane >> 2, qp = lane & 3;
    const int ub = tid >> 4;              // update: local batch 0..7 (tid<128)
    const int uu = tid & 15;              // update: unit
    const int gb = (bg << 3) + ub;        // global batch
    const int kbase = chunk << 5;

    if (tid < 8) sLen[tid] = p.len[(bg << 3) + tid];

    const float* whh = p.w[layer * 8 + dir * 4 + 1];
    const float* bih = p.w[layer * 8 + dir * 4 + 2];
    const float* bhh = p.w[layer * 8 + dir * 4 + 3];

    // ---- W_hh into mma A-fragments (bf16 hi/lo), loaded once ----
    unsigned wH[4][2][4], wL[4][2][4];
#pragma unroll
    for (int mt = 0; mt < 4; ++mt)
#pragma unroll
        for (int kt = 0; kt < 2; ++kt)
#pragma unroll
            for (int r = 0; r < 4; ++r) {
                int unit = grp + ((r & 1) << 3);                  // row&15
                int grow = (mt << 8) + j0a + unit;                // gate=mt
                int k = kbase + kt * 16 + (qp << 1) + ((r >> 1) << 3);
                float w0 = __ldg(whh + (size_t)grow * HID + k);
                float w1 = __ldg(whh + (size_t)grow * HID + k + 1);
                u16 h0 = bfu(w0), h1 = bfu(w1);
                wH[mt][kt][r] = (unsigned)h0 | ((unsigned)h1 << 16);
                u16 l0 = bfu(w0 - bff(h0)), l1 = bfu(w1 - bff(h1));
                wL[mt][kt][r] = (unsigned)l0 | ((unsigned)l1 << 16);
            }
    if (tid < 64) {
        int grow = ((tid >> 4) << 8) + j0a + (tid & 15);
        sBias[tid] = bih[grow] + bhh[grow];
    }
    // zero h buffers (both parities, hi+lo = 16896 B = 4224 u32)
    for (int i = tid; i < 4224; i += NTHREADS) ((unsigned*)smc)[i] = 0u;
    float creg = 0.f;
    __syncthreads();

    const int myLen = sLen[ub & 7];

    // zin sources + per-example time modes (0: t, 1: (t+len)%T, 2: (t+T-len)%T)
    const float *zsA, *zsB = nullptr;
    int mA, mB = 0;
    if (layer == 0)      { zsA = g_zin[dir]; mA = dir ? 1 : 0; }
    else if (dir == 0)   { zsA = g_zin[0]; mA = 0; zsB = g_zin[1]; mB = 2; }
    else                 { zsA = g_zin[2]; mA = 1; zsB = g_zin[3]; mB = 0; }

    auto tfix = [&](int mode, int s) -> int {
        int t = dir ? (TSEQ - 1 - s) : s;
        if (mode == 1) t += myLen;
        else if (mode == 2) t += TSEQ - myLen;
        if (t >= TSEQ) t -= TSEQ;
        return t;
    };

    float zA[4], zB[4];
    if (tid < 128) {
        size_t rA = (size_t)tfix(mA, 0) * BATCH + gb;
#pragma unroll
        for (int g = 0; g < 4; ++g) zA[g] = __ldg(zsA + rA * 1024 + (g << 8) + j0a + uu);
        if (zsB) {
            size_t rB = (size_t)tfix(mB, 0) * BATCH + gb;
#pragma unroll
            for (int g = 0; g < 4; ++g) zB[g] = __ldg(zsB + rB * 1024 + (g << 8) + j0a + uu);
        } else { zB[0] = zB[1] = zB[2] = zB[3] = 0.f; }
    }

    const uint32_t sbase = smem_u32(smc);
    u16* hist_h = dir ? g_bh : g_fh;
    u16* hist_l = dir ? g_bl : g_fl;

    CLUSTER_BAR();   // init (incl. h zeros) visible before any DSMEM pushes

    for (int s = 0; s < TSEQ; ++s) {
        const int par = s & 1;
        const int t = dir ? (TSEQ - 1 - s) : s;

        // ---- B fragments: h hi/lo from [b][264] layout (conflict-free) ----
        unsigned bH[2][2], bL[2][2];
        {
            const u16* hHp = hH + par * 8 * 264;
            const u16* hLp = hL + par * 8 * 264;
#pragma unroll
            for (int kt = 0; kt < 2; ++kt) {
                int off = grp * 264 + kbase + kt * 16 + (qp << 1);
                bH[kt][0] = *(const unsigned*)(hHp + off);
                bH[kt][1] = *(const unsigned*)(hHp + off + 8);
                bL[kt][0] = *(const unsigned*)(hLp + off);
                bL[kt][1] = *(const unsigned*)(hLp + off + 8);
            }
        }

        // ---- recurrent GEMM on tensor cores ----
        float acc[4][4];
#pragma unroll
        for (int mt = 0; mt < 4; ++mt)
#pragma unroll
            for (int q = 0; q < 4; ++q) acc[mt][q] = 0.f;
#pragma unroll
        for (int mt = 0; mt < 4; ++mt)
#pragma unroll
            for (int kt = 0; kt < 2; ++kt) {
                MMA16816(acc[mt], wH[mt][kt], bH[kt]);   // hi*hi
                MMA16816(acc[mt], wH[mt][kt], bL[kt]);   // hi*lo
                MMA16816(acc[mt], wL[mt][kt], bH[kt]);   // lo*hi
            }
        {
            float* zr = zp + chunk * 640;
#pragma unroll
            for (int mt = 0; mt < 4; ++mt) {
                int r0 = mt * 16 + grp;
                *(float2*)(zr + r0 * 10 + (qp << 1))       = make_float2(acc[mt][0], acc[mt][1]);
                *(float2*)(zr + (r0 + 8) * 10 + (qp << 1)) = make_float2(acc[mt][2], acc[mt][3]);
            }
        }
        __syncthreads();

        // ---- reduce + cell update: thread owns (unit uu, batch ub) ----
        if (tid < 128) {
            float zg4[4];
#pragma unroll
            for (int g = 0; g < 4; ++g) {
                int row = (g << 4) + uu;
                float v = zA[g] + zB[g] + sBias[row];
                const float* zpr = zp + row * 10 + ub;
#pragma unroll
                for (int c = 0; c < 8; ++c) v += zpr[c * 640];
                zg4[g] = v;
            }
            float ig = sigf(zg4[0]), fg = sigf(zg4[1]);
            float gg = tanhf(zg4[2]), og = sigf(zg4[3]);
            creg = fg * creg + ig * gg;
            float h = og * tanhf(creg);

            bool trig = dir ? (t == TSEQ - myLen) : (t == myLen - 1);
            if (trig) {
                size_t o = OUT_LH + ((size_t)(layer * 2 + dir) * BATCH + gb) * HID + j0a + uu;
                p.out[o] = h;
                p.out[o + LHN] = creg;
            }

            u16 hh = bfu(h);
            u16 hl = bfu(h - bff(hh));
            int lidx = (par ^ 1) * 8 * 264 + ub * 264 + j0a + uu;
            hH[lidx] = hh;
            hL[lidx] = hl;

            if (layer == 0) {
                size_t o = ((size_t)t * BATCH + gb) * HID + j0a + uu;
                hist_h[o] = hh;          // bf16 history consumed by layer-1 GEMMs
                hist_l[o] = hl;
            } else {
                int tm = t, col = j0a + uu;
                if (dir) { tm = t + myLen; if (tm >= TSEQ) tm -= TSEQ; col += HID; }
                p.out[((size_t)tm * BATCH + gb) * (2 * HID) + col] = (tm < myLen) ? h : 0.f;
            }

            // prefetch next step's z (addresses independent of h)
            if (s + 1 < TSEQ) {
                size_t rA = (size_t)tfix(mA, s + 1) * BATCH + gb;
#pragma unroll
                for (int g = 0; g < 4; ++g) zA[g] = __ldg(zsA + rA * 1024 + (g << 8) + j0a + uu);
                if (zsB) {
                    size_t rB = (size_t)tfix(mB, s + 1) * BATCH + gb;
#pragma unroll
                    for (int g = 0; g < 4; ++g) zB[g] = __ldg(zsB + rB * 1024 + (g << 8) + j0a + uu);
                }
            }
        }
        __syncthreads();

        // ---- DSMEM push: own 16-unit slice (hi+lo) -> 15 peers, 16B stores ----
        {
            const uint32_t po = (uint32_t)(((par ^ 1) * 8 * 264 + j0a) * 2);
#pragma unroll
            for (int it = 0; it < 2; ++it) {
                int item = tid + it * NTHREADS;           // 0..479 used
                if (item < 480) {
                    int rrk = (ug + 1 + (item >> 5)) & 15;
                    int c   = item & 31;
                    uint32_t off = (uint32_t)((c >> 4) * SCAN_HL) + po
                                 + (uint32_t)(((c >> 1) & 7) * 528) + (uint32_t)((c & 1) << 4);
                    float4 v = *(const float4*)(smc + off);
                    uint32_t rad;
                    asm("mapa.shared::cluster.u32 %0, %1, %2;"
                        : "=r"(rad) : "r"(sbase + off), "r"(rrk));
                    asm volatile("st.shared::cluster.v4.b32 [%0], {%1, %2, %3, %4};"
                                 :: "r"(rad), "r"(__float_as_uint(v.x)), "r"(__float_as_uint(v.y)),
                                    "r"(__float_as_uint(v.z)), "r"(__float_as_uint(v.w)) : "memory");
                }
            }
        }

        CLUSTER_BAR();   // h(par^1) visible cluster-wide; also orders zp reuse
    }
}

extern "C" void kernel_launch(void* const* d_in, const int* in_sizes, int n_in,
                              void* d_out, int out_size) {
    Params P;
    P.x   = (const float*)d_in[0];
    P.len = (const int*)d_in[1];
    for (int i = 0; i < 16; ++i) P.w[i] = (const float*)d_in[2 + i];
    P.out = (float*)d_out;

    void *zp_, *xh_, *xl_, *fh_, *fl_, *bh_, *bl_, *wh_, *wl_;
    cudaGetSymbolAddress(&zp_, g_zin);
    cudaGetSymbolAddress(&xh_, g_xh);  cudaGetSymbolAddress(&xl_, g_xl);
    cudaGetSymbolAddress(&fh_, g_fh);  cudaGetSymbolAddress(&fl_, g_fl);
    cudaGetSymbolAddress(&bh_, g_bh);  cudaGetSymbolAddress(&bl_, g_bl);
    cudaGetSymbolAddress(&wh_, g_wh);  cudaGetSymbolAddress(&wl_, g_wl);
    float* z = (float*)zp_;
    u16 *xh = (u16*)xh_, *xl = (u16*)xl_;
    u16 *fh = (u16*)fh_, *fl = (u16*)fl_;
    u16 *bh = (u16*)bh_, *bl = (u16*)bl_;
    u16 *wh = (u16*)wh_, *wl = (u16*)wl_;
    const size_t ZN = (size_t)MTOT * 1024;
    const size_t WV = 1024 * 256;

    cudaFuncSetAttribute(scan_kernel, cudaFuncAttributeNonPortableClusterSizeAllowed, 1);
    cudaFuncSetAttribute(scan_kernel, cudaFuncAttributeMaxDynamicSharedMemorySize, SCAN_SMEM);
    cudaFuncSetAttribute(gemm_bf16, cudaFuncAttributeMaxDynamicSharedMemorySize, GEMM_SMEM_BYTES);

    dim3 gg(16, 1024);   // N-tiles(64) x M-tiles(128)

    // k1: fused prep (x split + weight views)
    prep_kernel<<<dim3(MTOT * HID / 4 / 256, 2), 256>>>(P, wh, wl, xh, xl);

    // layer-0 input projections
    gemm_bf16<<<gg, 256, GEMM_SMEM_BYTES>>>(xh, xl, wh + 0 * WV, wl + 0 * WV, z);      // k2
    gemm_bf16<<<gg, 256, GEMM_SMEM_BYTES>>>(xh, xl, wh + 1 * WV, wl + 1 * WV, z + ZN); // k3

    scan_kernel<<<256, NTHREADS, SCAN_SMEM>>>(P, 0);                  // k4 <- ncu target

    // layer-1 input projections (K=512 split; A = scan0's bf16 h history)
    gemm_bf16<<<gg, 256, GEMM_SMEM_BYTES>>>(fh, fl, wh + 2 * WV, wl + 2 * WV, z);           // fwd, hsf
    gemm_bf16<<<gg, 256, GEMM_SMEM_BYTES>>>(bh, bl, wh + 3 * WV, wl + 3 * WV, z + ZN);      // fwd, hsb
    gemm_bf16<<<gg, 256, GEMM_SMEM_BYTES>>>(fh, fl, wh + 4 * WV, wl + 4 * WV, z + 2 * ZN);  // bwd, hsf
    gemm_bf16<<<gg, 256, GEMM_SMEM_BYTES>>>(bh, bl, wh + 5 * WV, wl + 5 * WV, z + 3 * ZN);  // bwd, hsb

    scan_kernel<<<256, NTHREADS, SCAN_SMEM>>>(P, 1);
}